// round 2
// baseline (speedup 1.0000x reference)
#include <cuda_runtime.h>
#include <cuda_bf16.h>
#include <math.h>

// Problem constants
#define BB 2
#define SS 2048
#define FF_IN 64
#define EE 512
#define HH 8
#define DH 64
#define LL 4
#define FFN 2048
#define MM (BB * SS)          // 4096 tokens
#define ATTN_SCALE 0.044194173824159216f   // 1/sqrt(512)

// ---------------------------------------------------------------------------
// Scratch (device globals; allocation-free per harness rules)
// ---------------------------------------------------------------------------
__device__ float g_X[MM * EE];
__device__ float g_Q[MM * EE];
__device__ float g_K[MM * EE];
__device__ float g_V[MM * EE];
__device__ float g_ATT[MM * EE];
__device__ float g_P[MM * EE];
__device__ float g_H1[MM * FFN];

// ---------------------------------------------------------------------------
// Embedding: X[m, :] = seq[m, :] @ W_emb + b_emb + pos_emb[s, :]
// grid = MM blocks, 128 threads (each thread: 4 contiguous output cols)
// ---------------------------------------------------------------------------
__global__ __launch_bounds__(128) void embed_kernel(
    const float* __restrict__ seq, const float* __restrict__ W,
    const float* __restrict__ bias, const float* __restrict__ pos,
    float* __restrict__ X)
{
    int m = blockIdx.x;
    int s = m & (SS - 1);
    int tid = threadIdx.x;
    __shared__ float srow[FF_IN];
    if (tid < FF_IN) srow[tid] = seq[(size_t)m * FF_IN + tid];
    __syncthreads();
    int n = tid * 4;
    float4 acc = *(const float4*)(bias + n);
    float4 pv  = *(const float4*)(pos + (size_t)s * EE + n);
    acc.x += pv.x; acc.y += pv.y; acc.z += pv.z; acc.w += pv.w;
    #pragma unroll 8
    for (int f = 0; f < FF_IN; f++) {
        float sv = srow[f];
        float4 w = *(const float4*)(W + (size_t)f * EE + n);
        acc.x += sv * w.x; acc.y += sv * w.y; acc.z += sv * w.z; acc.w += sv * w.w;
    }
    *(float4*)(X + (size_t)m * EE + n) = acc;
}

// ---------------------------------------------------------------------------
// SGEMM: C[M,N] = A[M,K] @ B[K,N] + bias[N]  (optional ReLU)
// BM=128, BN=64, BK=16; 256 threads; 8x4 micro-tile per thread.
// M, N, K all divisible by tile dims for this problem (no guards).
// ---------------------------------------------------------------------------
template <bool RELU>
__global__ __launch_bounds__(256) void sgemm_kernel(
    const float* __restrict__ A, const float* __restrict__ B,
    const float* __restrict__ bias, float* __restrict__ C,
    int N, int K)
{
    __shared__ float As[16][128];
    __shared__ float Bs[16][64];

    const int tid  = threadIdx.x;
    const int cRow = blockIdx.y * 128;
    const int cCol = blockIdx.x * 64;
    const int tr   = tid >> 4;        // 0..15 -> 8 rows each
    const int tc   = tid & 15;        // 0..15 -> 4 cols each
    const int aRow = tid >> 1;        // 0..127
    const int aCol = (tid & 1) * 8;   // 0 or 8
    const int bRow = tid >> 4;        // 0..15
    const int bCol = (tid & 15) * 4;  // 0..60

    float acc[8][4];
    #pragma unroll
    for (int i = 0; i < 8; i++)
        #pragma unroll
        for (int j = 0; j < 4; j++) acc[i][j] = 0.f;

    const float* Ap = A + (size_t)cRow * K;
    const float* Bp = B + cCol;

    for (int k0 = 0; k0 < K; k0 += 16) {
        float4 a0 = *(const float4*)(Ap + (size_t)aRow * K + k0 + aCol);
        float4 a1 = *(const float4*)(Ap + (size_t)aRow * K + k0 + aCol + 4);
        As[aCol + 0][aRow] = a0.x; As[aCol + 1][aRow] = a0.y;
        As[aCol + 2][aRow] = a0.z; As[aCol + 3][aRow] = a0.w;
        As[aCol + 4][aRow] = a1.x; As[aCol + 5][aRow] = a1.y;
        As[aCol + 6][aRow] = a1.z; As[aCol + 7][aRow] = a1.w;
        float4 bv = *(const float4*)(Bp + (size_t)(k0 + bRow) * N + bCol);
        *(float4*)&Bs[bRow][bCol] = bv;
        __syncthreads();

        #pragma unroll
        for (int k = 0; k < 16; k++) {
            float ar[8], br[4];
            *(float4*)&ar[0] = *(const float4*)&As[k][tr * 8];
            *(float4*)&ar[4] = *(const float4*)&As[k][tr * 8 + 4];
            *(float4*)&br[0] = *(const float4*)&Bs[k][tc * 4];
            #pragma unroll
            for (int i = 0; i < 8; i++)
                #pragma unroll
                for (int j = 0; j < 4; j++)
                    acc[i][j] += ar[i] * br[j];
        }
        __syncthreads();
    }

    float4 bb = *(const float4*)(bias + cCol + tc * 4);
    #pragma unroll
    for (int i = 0; i < 8; i++) {
        float4 r;
        r.x = acc[i][0] + bb.x;
        r.y = acc[i][1] + bb.y;
        r.z = acc[i][2] + bb.z;
        r.w = acc[i][3] + bb.w;
        if (RELU) {
            r.x = fmaxf(r.x, 0.f); r.y = fmaxf(r.y, 0.f);
            r.z = fmaxf(r.z, 0.f); r.w = fmaxf(r.w, 0.f);
        }
        *(float4*)(C + (size_t)(cRow + tr * 8 + i) * N + cCol + tc * 4) = r;
    }
}

// ---------------------------------------------------------------------------
// Flash attention. One CTA: 64 query rows x one (batch, head). Loops over
// 64-key tiles with online softmax. K tile buffer is reused to hold P.
// Dynamic smem: Qs[64][64] (swizzled), KP[64][64] (swizzled), Vs[64][68], Ms[64].
// grid = (S/64, B*H), 256 threads (16x16).
// ---------------------------------------------------------------------------
#define ATTN_SMEM ((64 * 64 + 64 * 64 + 64 * 68) * 4 + 64 * 4)

__global__ __launch_bounds__(256) void attn_kernel(
    const float* __restrict__ Qg, const float* __restrict__ Kg,
    const float* __restrict__ Vg, const int* __restrict__ mask,
    float* __restrict__ Og)
{
    extern __shared__ float smem[];
    float* Qs = smem;                 // 64*64, xor-swizzled
    float* KP = smem + 4096;          // 64*64, xor-swizzled (K, then P)
    float* Vs = smem + 8192;          // 64*68 padded
    int*   Ms = (int*)(smem + 12544); // 64

    const int tid = threadIdx.x;
    const int ty  = tid >> 4;   // 0..15
    const int tx  = tid & 15;   // 0..15
    const int ty4 = ty * 4;
    const int tx4 = tx * 4;
    const int sQ  = ty & 7;     // swizzle key for rows ty4..ty4+3
    const int sK  = tx & 7;     // swizzle key for rows tx4..tx4+3

    const int bh = blockIdx.y;
    const int b  = bh >> 3;
    const int h  = bh & 7;
    const int qrow0 = blockIdx.x * 64;

    // cooperative load mapping: each thread 1 row (lr), 4 float4 groups
    const int lr  = tid >> 2;          // 0..63
    const int lcg = (tid & 3) * 4;     // base float4-group
    const int swl = (lr >> 2) & 7;

    // Load Q (scaled) into swizzled Qs
    {
        const float* qp = Qg + (size_t)(b * SS + qrow0 + lr) * EE + h * DH;
        #pragma unroll
        for (int u = 0; u < 4; u++) {
            int d4 = lcg + u;
            float4 v = *(const float4*)(qp + d4 * 4);
            v.x *= ATTN_SCALE; v.y *= ATTN_SCALE; v.z *= ATTN_SCALE; v.w *= ATTN_SCALE;
            *(float4*)&Qs[lr * 64 + ((d4 ^ swl) << 2)] = v;
        }
    }

    float m_i[4], l_i[4], o[4][4];
    #pragma unroll
    for (int i = 0; i < 4; i++) {
        m_i[i] = -INFINITY; l_i[i] = 0.f;
        #pragma unroll
        for (int j = 0; j < 4; j++) o[i][j] = 0.f;
    }

    for (int kt = 0; kt < SS / 64; kt++) {
        __syncthreads();   // prev-iter P@V reads done (and Q visible on iter 0)
        {
            const float* kp = Kg + (size_t)(b * SS + kt * 64 + lr) * EE + h * DH;
            const float* vp = Vg + (size_t)(b * SS + kt * 64 + lr) * EE + h * DH;
            #pragma unroll
            for (int u = 0; u < 4; u++) {
                int d4 = lcg + u;
                float4 kv = *(const float4*)(kp + d4 * 4);
                *(float4*)&KP[lr * 64 + ((d4 ^ swl) << 2)] = kv;
                float4 vv = *(const float4*)(vp + d4 * 4);
                *(float4*)&Vs[lr * 68 + d4 * 4] = vv;
            }
            if (tid < 64) Ms[tid] = mask[b * SS + kt * 64 + tid];
        }
        __syncthreads();

        // S tile = Qs @ KP^T  (each thread 4x4)
        float s[4][4];
        #pragma unroll
        for (int i = 0; i < 4; i++)
            #pragma unroll
            for (int j = 0; j < 4; j++) s[i][j] = 0.f;

        #pragma unroll 4
        for (int d4 = 0; d4 < 16; d4++) {
            float4 qv[4], kv[4];
            #pragma unroll
            for (int i = 0; i < 4; i++)
                qv[i] = *(const float4*)&Qs[(ty4 + i) * 64 + ((d4 ^ sQ) << 2)];
            #pragma unroll
            for (int j = 0; j < 4; j++)
                kv[j] = *(const float4*)&KP[(tx4 + j) * 64 + ((d4 ^ sK) << 2)];
            #pragma unroll
            for (int i = 0; i < 4; i++)
                #pragma unroll
                for (int j = 0; j < 4; j++)
                    s[i][j] += qv[i].x * kv[j].x + qv[i].y * kv[j].y +
                               qv[i].z * kv[j].z + qv[i].w * kv[j].w;
        }

        // mask (all-ones in this dataset, honored anyway)
        #pragma unroll
        for (int j = 0; j < 4; j++) {
            if (Ms[tx4 + j] == 0) {
                #pragma unroll
                for (int i = 0; i < 4; i++) s[i][j] = -1e20f;
            }
        }

        // online softmax update (row stats reduced over the 16-lane tx group)
        #pragma unroll
        for (int i = 0; i < 4; i++) {
            float mx = fmaxf(fmaxf(s[i][0], s[i][1]), fmaxf(s[i][2], s[i][3]));
            #pragma unroll
            for (int off = 8; off; off >>= 1)
                mx = fmaxf(mx, __shfl_xor_sync(0xffffffffu, mx, off));
            float mnew = fmaxf(m_i[i], mx);
            float corr = __expf(m_i[i] - mnew);
            float rs = 0.f;
            #pragma unroll
            for (int j = 0; j < 4; j++) {
                float p = __expf(s[i][j] - mnew);
                s[i][j] = p;
                rs += p;
            }
            #pragma unroll
            for (int off = 8; off; off >>= 1)
                rs += __shfl_xor_sync(0xffffffffu, rs, off);
            l_i[i] = l_i[i] * corr + rs;
            m_i[i] = mnew;
            #pragma unroll
            for (int j = 0; j < 4; j++) o[i][j] *= corr;
        }

        __syncthreads();   // everyone finished reading K tile

        // store P into KP (same swizzle: d4 ^ (row>>2 & 7); here row>>2 == ty)
        #pragma unroll
        for (int i = 0; i < 4; i++) {
            float4 pv = make_float4(s[i][0], s[i][1], s[i][2], s[i][3]);
            *(float4*)&KP[(ty4 + i) * 64 + ((tx ^ sQ) << 2)] = pv;
        }
        __syncthreads();

        // O += P @ V
        #pragma unroll 2
        for (int k4 = 0; k4 < 16; k4++) {
            float4 pr[4], vv[4];
            #pragma unroll
            for (int i = 0; i < 4; i++)
                pr[i] = *(const float4*)&KP[(ty4 + i) * 64 + ((k4 ^ sQ) << 2)];
            #pragma unroll
            for (int jj = 0; jj < 4; jj++)
                vv[jj] = *(const float4*)&Vs[(k4 * 4 + jj) * 68 + tx4];
            #pragma unroll
            for (int i = 0; i < 4; i++) {
                o[i][0] += pr[i].x * vv[0].x + pr[i].y * vv[1].x + pr[i].z * vv[2].x + pr[i].w * vv[3].x;
                o[i][1] += pr[i].x * vv[0].y + pr[i].y * vv[1].y + pr[i].z * vv[2].y + pr[i].w * vv[3].y;
                o[i][2] += pr[i].x * vv[0].z + pr[i].y * vv[1].z + pr[i].z * vv[2].z + pr[i].w * vv[3].z;
                o[i][3] += pr[i].x * vv[0].w + pr[i].y * vv[1].w + pr[i].z * vv[2].w + pr[i].w * vv[3].w;
            }
        }
    }

    // finalize and write out
    #pragma unroll
    for (int i = 0; i < 4; i++) {
        float inv = 1.f / l_i[i];
        float4 r = make_float4(o[i][0] * inv, o[i][1] * inv, o[i][2] * inv, o[i][3] * inv);
        *(float4*)(Og + (size_t)(b * SS + qrow0 + ty4 + i) * EE + h * DH + tx4) = r;
    }
}

// ---------------------------------------------------------------------------
// Fused residual + LayerNorm: out[m,:] = LN(a[m,:] + br[m,:]) * g + be
// grid = MM blocks, 128 threads.
// ---------------------------------------------------------------------------
__global__ __launch_bounds__(128) void ln_kernel(
    const float* __restrict__ a, const float* __restrict__ br,
    const float* __restrict__ g, const float* __restrict__ be,
    float* __restrict__ out)
{
    int m = blockIdx.x;
    int tid = threadIdx.x;
    size_t base = (size_t)m * EE + tid * 4;
    float4 va = *(const float4*)(a + base);
    float4 vb = *(const float4*)(br + base);
    float x0 = va.x + vb.x, x1 = va.y + vb.y, x2 = va.z + vb.z, x3 = va.w + vb.w;
    float s  = x0 + x1 + x2 + x3;
    float ss = x0 * x0 + x1 * x1 + x2 * x2 + x3 * x3;
    #pragma unroll
    for (int off = 16; off; off >>= 1) {
        s  += __shfl_xor_sync(0xffffffffu, s, off);
        ss += __shfl_xor_sync(0xffffffffu, ss, off);
    }
    __shared__ float red[8];
    int w = tid >> 5, ln = tid & 31;
    if (ln == 0) { red[w] = s; red[4 + w] = ss; }
    __syncthreads();
    s  = red[0] + red[1] + red[2] + red[3];
    ss = red[4] + red[5] + red[6] + red[7];
    float mean = s * (1.f / EE);
    float var  = ss * (1.f / EE) - mean * mean;
    float r = rsqrtf(var + 1e-5f);
    float4 gg = *(const float4*)(g + tid * 4);
    float4 bb = *(const float4*)(be + tid * 4);
    float4 o;
    o.x = (x0 - mean) * r * gg.x + bb.x;
    o.y = (x1 - mean) * r * gg.y + bb.y;
    o.z = (x2 - mean) * r * gg.z + bb.z;
    o.w = (x3 - mean) * r * gg.w + bb.w;
    *(float4*)(out + base) = o;
}

// ---------------------------------------------------------------------------
// Launch
// ---------------------------------------------------------------------------
extern "C" void kernel_launch(void* const* d_in, const int* in_sizes, int n_in,
                              void* d_out, int out_size)
{
    const float* seq   = (const float*)d_in[0];
    const int*   mask  = (const int*)  d_in[1];
    const float* W_emb = (const float*)d_in[2];
    const float* b_emb = (const float*)d_in[3];
    const float* pos   = (const float*)d_in[4];
    const float* Wq    = (const float*)d_in[5];
    const float* bq    = (const float*)d_in[6];
    const float* Wk    = (const float*)d_in[7];
    const float* bk    = (const float*)d_in[8];
    const float* Wv    = (const float*)d_in[9];
    const float* bv    = (const float*)d_in[10];
    const float* Wo    = (const float*)d_in[11];
    const float* bo    = (const float*)d_in[12];
    const float* ln1g  = (const float*)d_in[13];
    const float* ln1b  = (const float*)d_in[14];
    const float* ln2g  = (const float*)d_in[15];
    const float* ln2b  = (const float*)d_in[16];
    const float* W1    = (const float*)d_in[17];
    const float* b1    = (const float*)d_in[18];
    const float* W2    = (const float*)d_in[19];
    const float* b2    = (const float*)d_in[20];
    float* out = (float*)d_out;

    float *X, *Q, *K, *V, *ATT, *P, *H1;
    cudaGetSymbolAddress((void**)&X,   g_X);
    cudaGetSymbolAddress((void**)&Q,   g_Q);
    cudaGetSymbolAddress((void**)&K,   g_K);
    cudaGetSymbolAddress((void**)&V,   g_V);
    cudaGetSymbolAddress((void**)&ATT, g_ATT);
    cudaGetSymbolAddress((void**)&P,   g_P);
    cudaGetSymbolAddress((void**)&H1,  g_H1);

    cudaFuncSetAttribute(attn_kernel, cudaFuncAttributeMaxDynamicSharedMemorySize,
                         ATTN_SMEM);

    embed_kernel<<<MM, 128>>>(seq, W_emb, b_emb, pos, X);

    dim3 gemmE(EE / 64, MM / 128);     // N=512
    dim3 gemmF(FFN / 64, MM / 128);    // N=2048
    dim3 attnG(SS / 64, BB * HH);

    for (int l = 0; l < LL; l++) {
        size_t oW  = (size_t)l * EE * EE;
        size_t oB  = (size_t)l * EE;
        size_t oW1 = (size_t)l * EE * FFN;
        size_t oB1 = (size_t)l * FFN;
        size_t oW2 = (size_t)l * FFN * EE;

        sgemm_kernel<false><<<gemmE, 256>>>(X, Wq + oW, bq + oB, Q, EE, EE);
        sgemm_kernel<false><<<gemmE, 256>>>(X, Wk + oW, bk + oB, K, EE, EE);
        sgemm_kernel<false><<<gemmE, 256>>>(X, Wv + oW, bv + oB, V, EE, EE);

        attn_kernel<<<attnG, 256, ATTN_SMEM>>>(Q, K, V, mask, ATT);

        sgemm_kernel<false><<<gemmE, 256>>>(ATT, Wo + oW, bo + oB, P, EE, EE);
        ln_kernel<<<MM, 128>>>(X, P, ln1g + oB, ln1b + oB, X);

        sgemm_kernel<true ><<<gemmF, 256>>>(X, W1 + oW1, b1 + oB1, H1, FFN, EE);
        sgemm_kernel<false><<<gemmE, 256>>>(H1, W2 + oW2, b2 + oB, P, EE, FFN);

        float* dst = (l == LL - 1) ? out : X;
        ln_kernel<<<MM, 128>>>(X, P, ln2g + oB, ln2b + oB, dst);
    }
}

// round 4
// speedup vs baseline: 1.3869x; 1.3869x over previous
#include <cuda_runtime.h>
#include <cuda_bf16.h>
#include <math.h>
#include <stdint.h>

#define BB 2
#define SS 2048
#define FF_IN 64
#define EE 512
#define HH 8
#define DH 64
#define LL 4
#define FFN 2048
#define MM (BB * SS)
#define ATTN_SCALE 0.044194173824159216f

// ---------------- helpers ----------------
__device__ __forceinline__ uint32_t smem_u32(const void* p) {
    uint32_t a;
    asm("{ .reg .u64 t; cvta.to.shared.u64 t, %1; cvt.u32.u64 %0, t; }" : "=r"(a) : "l"(p));
    return a;
}
#define SWZ128(o) ((o) ^ (((o) >> 3) & 0x70))

__device__ __forceinline__ void cp16(uint32_t s, const void* g) {
    asm volatile("cp.async.cg.shared.global [%0], [%1], 16;" :: "r"(s), "l"(g) : "memory");
}
#define CP_COMMIT() asm volatile("cp.async.commit_group;" ::: "memory")

__device__ __forceinline__ void ldsm4(uint32_t* d, uint32_t a) {
    asm volatile("ldmatrix.sync.aligned.m8n8.x4.shared.b16 {%0,%1,%2,%3}, [%4];"
                 : "=r"(d[0]), "=r"(d[1]), "=r"(d[2]), "=r"(d[3]) : "r"(a));
}
__device__ __forceinline__ void mma_bf16(float* c, const uint32_t* a, const uint32_t* b) {
    asm volatile("mma.sync.aligned.m16n8k16.row.col.f32.bf16.bf16.f32 "
        "{%0,%1,%2,%3}, {%4,%5,%6,%7}, {%8,%9}, {%0,%1,%2,%3};"
        : "+f"(c[0]), "+f"(c[1]), "+f"(c[2]), "+f"(c[3])
        : "r"(a[0]), "r"(a[1]), "r"(a[2]), "r"(a[3]), "r"(b[0]), "r"(b[1]));
}

// quad split: A slots (ah,ah,al,al); B slots (bh,bl,bh,bl)
__device__ __forceinline__ uint2 quad_a(float f) {
    __nv_bfloat16 h = __float2bfloat16(f);
    __nv_bfloat16 l = __float2bfloat16(f - __bfloat162float(h));
    return make_uint2((uint32_t)__bfloat16_as_ushort(h) * 0x10001u,
                      (uint32_t)__bfloat16_as_ushort(l) * 0x10001u);
}
__device__ __forceinline__ uint2 quad_b(float f) {
    __nv_bfloat16 h = __float2bfloat16(f);
    __nv_bfloat16 l = __float2bfloat16(f - __bfloat162float(h));
    uint32_t w = (uint32_t)__bfloat16_as_ushort(h) | ((uint32_t)__bfloat16_as_ushort(l) << 16);
    return make_uint2(w, w);
}

// ---------------- scratch ----------------
__device__ float g_X[MM * EE];
__device__ float g_ATT[MM * EE];
__device__ float g_P[MM * EE];
__device__ float g_QKV[MM * 1536];
__device__ float g_bqkv[LL * 1536];
__device__ uint2 g_X4[MM * EE];
__device__ uint2 g_ATT4[MM * EE];
__device__ uint2 g_H14[MM * FFN];
__device__ uint2 g_QKVW4[LL][1536 * EE];
__device__ uint2 g_WO4[LL][EE * EE];
__device__ uint2 g_W14[LL][FFN * EE];
__device__ uint2 g_W24[LL][EE * FFN];

// W[K][N] fp32 -> B4[N][K] quads
__global__ __launch_bounds__(256) void prepW_kernel(
    const float* __restrict__ W, uint2* __restrict__ B4, int K, int N)
{
    __shared__ uint2 t[32][33];
    int k0 = blockIdx.y * 32, n0 = blockIdx.x * 32;
    int tx = threadIdx.x, ty = threadIdx.y;
    #pragma unroll
    for (int i = 0; i < 4; i++)
        t[ty + i * 8][tx] = quad_b(W[(size_t)(k0 + ty + i * 8) * N + n0 + tx]);
    __syncthreads();
    #pragma unroll
    for (int i = 0; i < 4; i++)
        B4[(size_t)(n0 + ty + i * 8) * K + k0 + tx] = t[tx][ty + i * 8];
}

__global__ __launch_bounds__(256) void cvtA_kernel(
    const float* __restrict__ A, uint2* __restrict__ A4, int n)
{
    int i = blockIdx.x * 256 + threadIdx.x;
    if (i < n) A4[i] = quad_a(A[i]);
}

__global__ __launch_bounds__(256) void biascat_kernel(
    const float* __restrict__ bq, const float* __restrict__ bk,
    const float* __restrict__ bv, float* __restrict__ o)
{
    int i = blockIdx.x * 256 + threadIdx.x;
    if (i >= LL * 1536) return;
    int l = i / 1536, j = i - l * 1536;
    o[i] = (j < 512) ? bq[l * 512 + j] : (j < 1024) ? bk[l * 512 + j - 512] : bv[l * 512 + j - 1024];
}

// ---------------- HMMA GEMM ----------------
// C[M,N] = quadA[M,K4] x quadB[N,K4] + bias. Tile 128x128, BK=64 bf16,
// 256 threads (8 warps 4x2, warp tile 32x64), cp.async double buffer.
#define GSMEM 65536
template <int OUTQ>
__global__ __launch_bounds__(256, 2) void hmma_gemm(
    const uint2* __restrict__ A4, const uint2* __restrict__ B4,
    const float* __restrict__ bias, void* __restrict__ Cout, int ldc, int K4)
{
    extern __shared__ char smem[];
    const uint32_t sb = smem_u32(smem);
    const int tid = threadIdx.x, lane = tid & 31, wid = tid >> 5;
    const int wm = (wid >> 1) * 32, wn = (wid & 1) * 64;
    const int cRow = blockIdx.y * 128, cCol = blockIdx.x * 128;
    const size_t rowbytes = (size_t)K4 * 2;
    const char* Abase = (const char*)(A4 + (size_t)cRow * (K4 >> 2));
    const char* Bbase = (const char*)(B4 + (size_t)cCol * (K4 >> 2));

    float acc[2][8][4];
    #pragma unroll
    for (int a = 0; a < 2; a++)
        #pragma unroll
        for (int b = 0; b < 8; b++)
            #pragma unroll
            for (int c = 0; c < 4; c++) acc[a][b][c] = 0.f;

    const int lr = tid >> 3;           // 0..31
    const int lc = (tid & 7) * 16;     // byte chunk in 128B row

    auto load_stage = [&](int s) {
        uint32_t dA = sb + (s & 1) * 32768;
        uint32_t dB = dA + 16384;
        size_t kb = (size_t)s * 128;
        #pragma unroll
        for (int i = 0; i < 4; i++) {
            int r = lr + i * 32;
            cp16(dA + SWZ128(r * 128 + lc), Abase + (size_t)r * rowbytes + kb + lc);
        }
        #pragma unroll
        for (int i = 0; i < 4; i++) {
            int r = lr + i * 32;
            cp16(dB + SWZ128(r * 128 + lc), Bbase + (size_t)r * rowbytes + kb + lc);
        }
    };

    const int NS = K4 / 64;
    load_stage(0); CP_COMMIT();
    for (int s = 0; s < NS; s++) {
        if (s + 1 < NS) {
            load_stage(s + 1); CP_COMMIT();
            asm volatile("cp.async.wait_group 1;" ::: "memory");
        } else {
            asm volatile("cp.async.wait_group 0;" ::: "memory");
        }
        __syncthreads();
        uint32_t sA = sb + (s & 1) * 32768, sB = sA + 16384;
        #pragma unroll
        for (int ks = 0; ks < 4; ks++) {
            int bc = ks * 32;
            uint32_t af[2][4], bf[4][4];
            #pragma unroll
            for (int mt = 0; mt < 2; mt++) {
                int row = wm + mt * 16 + ((lane >> 3) & 1) * 8 + (lane & 7);
                int col = bc + (lane >> 4) * 16;
                ldsm4(af[mt], sA + SWZ128(row * 128 + col));
            }
            #pragma unroll
            for (int p = 0; p < 4; p++) {
                int row = wn + p * 16 + ((lane >> 4) & 1) * 8 + (lane & 7);
                int col = bc + ((lane >> 3) & 1) * 16;
                ldsm4(bf[p], sB + SWZ128(row * 128 + col));
            }
            #pragma unroll
            for (int mt = 0; mt < 2; mt++)
                #pragma unroll
                for (int nt = 0; nt < 8; nt++)
                    mma_bf16(acc[mt][nt], af[mt], &bf[nt >> 1][(nt & 1) * 2]);
        }
        __syncthreads();
    }

    // epilogue: fragment c0,c1 rows +0; c2,c3 rows +8
    #pragma unroll
    for (int mt = 0; mt < 2; mt++)
        #pragma unroll
        for (int rp = 0; rp < 2; rp++) {
            int row = cRow + wm + mt * 16 + rp * 8 + (lane >> 2);
            #pragma unroll
            for (int nt = 0; nt < 8; nt++) {
                int col = cCol + wn + nt * 8 + (lane & 3) * 2;
                float2 bz = *(const float2*)(bias + col);
                float v0 = acc[mt][nt][rp * 2]     + bz.x;
                float v1 = acc[mt][nt][rp * 2 + 1] + bz.y;
                if (OUTQ) {
                    v0 = fmaxf(v0, 0.f); v1 = fmaxf(v1, 0.f);
                    uint2 q0 = quad_a(v0), q1 = quad_a(v1);
                    *(uint4*)((uint2*)Cout + (size_t)row * ldc + col) =
                        make_uint4(q0.x, q0.y, q1.x, q1.y);
                } else {
                    *(float2*)((float*)Cout + (size_t)row * ldc + col) =
                        make_float2(v0, v1);
                }
            }
        }
}

// ---------------- embedding ----------------
__global__ __launch_bounds__(128) void embed_kernel(
    const float* __restrict__ seq, const float* __restrict__ W,
    const float* __restrict__ bias, const float* __restrict__ pos,
    float* __restrict__ X)
{
    int m = blockIdx.x, s = m & (SS - 1), tid = threadIdx.x;
    __shared__ float srow[FF_IN];
    if (tid < FF_IN) srow[tid] = seq[(size_t)m * FF_IN + tid];
    __syncthreads();
    int n = tid * 4;
    float4 acc = *(const float4*)(bias + n);
    float4 pv  = *(const float4*)(pos + (size_t)s * EE + n);
    acc.x += pv.x; acc.y += pv.y; acc.z += pv.z; acc.w += pv.w;
    #pragma unroll 8
    for (int f = 0; f < FF_IN; f++) {
        float sv = srow[f];
        float4 w = *(const float4*)(W + (size_t)f * EE + n);
        acc.x += sv * w.x; acc.y += sv * w.y; acc.z += sv * w.z; acc.w += sv * w.w;
    }
    *(float4*)(X + (size_t)m * EE + n) = acc;
}

// ---------------- flash attention (QKV fused input, stride 1536) ----------------
#define ATTN_SMEM ((64 * 64 + 64 * 64 + 64 * 68) * 4 + 64 * 4)
__global__ __launch_bounds__(256) void attn_kernel(
    const float* __restrict__ QKV, const int* __restrict__ mask, float* __restrict__ Og)
{
    extern __shared__ float smf[];
    float* Qs = smf;
    float* KP = smf + 4096;
    float* Vs = smf + 8192;
    int*   Ms = (int*)(smf + 12544);

    const int tid = threadIdx.x, ty = tid >> 4, tx = tid & 15;
    const int ty4 = ty * 4, tx4 = tx * 4, sQ = ty & 7, sK = tx & 7;
    const int b = blockIdx.y >> 3, h = blockIdx.y & 7;
    const int qrow0 = blockIdx.x * 64;
    const int lr = tid >> 2, lcg = (tid & 3) * 4, swl = (lr >> 2) & 7;

    {
        const float* qp = QKV + (size_t)(b * SS + qrow0 + lr) * 1536 + h * DH;
        #pragma unroll
        for (int u = 0; u < 4; u++) {
            int d4 = lcg + u;
            float4 v = *(const float4*)(qp + d4 * 4);
            v.x *= ATTN_SCALE; v.y *= ATTN_SCALE; v.z *= ATTN_SCALE; v.w *= ATTN_SCALE;
            *(float4*)&Qs[lr * 64 + ((d4 ^ swl) << 2)] = v;
        }
    }

    float m_i[4], l_i[4], o[4][4];
    #pragma unroll
    for (int i = 0; i < 4; i++) {
        m_i[i] = -INFINITY; l_i[i] = 0.f;
        #pragma unroll
        for (int j = 0; j < 4; j++) o[i][j] = 0.f;
    }

    for (int kt = 0; kt < SS / 64; kt++) {
        __syncthreads();
        {
            const float* kp = QKV + (size_t)(b * SS + kt * 64 + lr) * 1536 + 512 + h * DH;
            #pragma unroll
            for (int u = 0; u < 4; u++) {
                int d4 = lcg + u;
                float4 kv = *(const float4*)(kp + d4 * 4);
                *(float4*)&KP[lr * 64 + ((d4 ^ swl) << 2)] = kv;
                float4 vv = *(const float4*)(kp + 512 + d4 * 4);
                *(float4*)&Vs[lr * 68 + d4 * 4] = vv;
            }
            if (tid < 64) Ms[tid] = mask[b * SS + kt * 64 + tid];
        }
        __syncthreads();

        float s[4][4];
        #pragma unroll
        for (int i = 0; i < 4; i++)
            #pragma unroll
            for (int j = 0; j < 4; j++) s[i][j] = 0.f;

        #pragma unroll 4
        for (int d4 = 0; d4 < 16; d4++) {
            float4 qv[4], kv[4];
            #pragma unroll
            for (int i = 0; i < 4; i++)
                qv[i] = *(const float4*)&Qs[(ty4 + i) * 64 + ((d4 ^ sQ) << 2)];
            #pragma unroll
            for (int j = 0; j < 4; j++)
                kv[j] = *(const float4*)&KP[(tx4 + j) * 64 + ((d4 ^ sK) << 2)];
            #pragma unroll
            for (int i = 0; i < 4; i++)
                #pragma unroll
                for (int j = 0; j < 4; j++)
                    s[i][j] += qv[i].x * kv[j].x + qv[i].y * kv[j].y +
                               qv[i].z * kv[j].z + qv[i].w * kv[j].w;
        }

        #pragma unroll
        for (int j = 0; j < 4; j++)
            if (Ms[tx4 + j] == 0) {
                #pragma unroll
                for (int i = 0; i < 4; i++) s[i][j] = -1e20f;
            }

        #pragma unroll
        for (int i = 0; i < 4; i++) {
            float mx = fmaxf(fmaxf(s[i][0], s[i][1]), fmaxf(s[i][2], s[i][3]));
            #pragma unroll
            for (int off = 8; off; off >>= 1)
                mx = fmaxf(mx, __shfl_xor_sync(0xffffffffu, mx, off));
            float mnew = fmaxf(m_i[i], mx);
            float corr = __expf(m_i[i] - mnew);
            float rs = 0.f;
            #pragma unroll
            for (int j = 0; j < 4; j++) {
                float p = __expf(s[i][j] - mnew);
                s[i][j] = p; rs += p;
            }
            #pragma unroll
            for (int off = 8; off; off >>= 1)
                rs += __shfl_xor_sync(0xffffffffu, rs, off);
            l_i[i] = l_i[i] * corr + rs;
            m_i[i] = mnew;
            #pragma unroll
            for (int j = 0; j < 4; j++) o[i][j] *= corr;
        }

        __syncthreads();
        #pragma unroll
        for (int i = 0; i < 4; i++)
            *(float4*)&KP[(ty4 + i) * 64 + ((tx ^ sQ) << 2)] =
                make_float4(s[i][0], s[i][1], s[i][2], s[i][3]);
        __syncthreads();

        #pragma unroll 2
        for (int k4 = 0; k4 < 16; k4++) {
            float4 pr[4], vv[4];
            #pragma unroll
            for (int i = 0; i < 4; i++)
                pr[i] = *(const float4*)&KP[(ty4 + i) * 64 + ((k4 ^ sQ) << 2)];
            #pragma unroll
            for (int jj = 0; jj < 4; jj++)
                vv[jj] = *(const float4*)&Vs[(k4 * 4 + jj) * 68 + tx4];
            #pragma unroll
            for (int i = 0; i < 4; i++) {
                o[i][0] += pr[i].x * vv[0].x + pr[i].y * vv[1].x + pr[i].z * vv[2].x + pr[i].w * vv[3].x;
                o[i][1] += pr[i].x * vv[0].y + pr[i].y * vv[1].y + pr[i].z * vv[2].y + pr[i].w * vv[3].y;
                o[i][2] += pr[i].x * vv[0].z + pr[i].y * vv[1].z + pr[i].z * vv[2].z + pr[i].w * vv[3].z;
                o[i][3] += pr[i].x * vv[0].w + pr[i].y * vv[1].w + pr[i].z * vv[2].w + pr[i].w * vv[3].w;
            }
        }
    }

    #pragma unroll
    for (int i = 0; i < 4; i++) {
        float inv = 1.f / l_i[i];
        *(float4*)(Og + (size_t)(b * SS + qrow0 + ty4 + i) * EE + h * DH + tx4) =
            make_float4(o[i][0] * inv, o[i][1] * inv, o[i][2] * inv, o[i][3] * inv);
    }
}

// ---------------- residual + LN ----------------
__global__ __launch_bounds__(128) void ln_kernel(
    const float* __restrict__ a, const float* __restrict__ br,
    const float* __restrict__ g, const float* __restrict__ be, float* __restrict__ out)
{
    int m = blockIdx.x, tid = threadIdx.x;
    size_t base = (size_t)m * EE + tid * 4;
    float4 va = *(const float4*)(a + base);
    float4 vb = *(const float4*)(br + base);
    float x0 = va.x + vb.x, x1 = va.y + vb.y, x2 = va.z + vb.z, x3 = va.w + vb.w;
    float s = x0 + x1 + x2 + x3;
    float ss = x0 * x0 + x1 * x1 + x2 * x2 + x3 * x3;
    #pragma unroll
    for (int off = 16; off; off >>= 1) {
        s  += __shfl_xor_sync(0xffffffffu, s, off);
        ss += __shfl_xor_sync(0xffffffffu, ss, off);
    }
    __shared__ float red[8];
    int w = tid >> 5;
    if ((tid & 31) == 0) { red[w] = s; red[4 + w] = ss; }
    __syncthreads();
    s  = red[0] + red[1] + red[2] + red[3];
    ss = red[4] + red[5] + red[6] + red[7];
    float mean = s * (1.f / EE);
    float var  = ss * (1.f / EE) - mean * mean;
    float r = rsqrtf(var + 1e-5f);
    float4 gg = *(const float4*)(g + tid * 4);
    float4 bb = *(const float4*)(be + tid * 4);
    float4 o;
    o.x = (x0 - mean) * r * gg.x + bb.x;
    o.y = (x1 - mean) * r * gg.y + bb.y;
    o.z = (x2 - mean) * r * gg.z + bb.z;
    o.w = (x3 - mean) * r * gg.w + bb.w;
    *(float4*)(out + base) = o;
}

// ---------------- launch ----------------
extern "C" void kernel_launch(void* const* d_in, const int* in_sizes, int n_in,
                              void* d_out, int out_size)
{
    const float* seq   = (const float*)d_in[0];
    const int*   mask  = (const int*)  d_in[1];
    const float* W_emb = (const float*)d_in[2];
    const float* b_emb = (const float*)d_in[3];
    const float* pos   = (const float*)d_in[4];
    const float* Wq    = (const float*)d_in[5];
    const float* bq    = (const float*)d_in[6];
    const float* Wk    = (const float*)d_in[7];
    const float* bk    = (const float*)d_in[8];
    const float* Wv    = (const float*)d_in[9];
    const float* bv    = (const float*)d_in[10];
    const float* Wo    = (const float*)d_in[11];
    const float* bo    = (const float*)d_in[12];
    const float* ln1g  = (const float*)d_in[13];
    const float* ln1b  = (const float*)d_in[14];
    const float* ln2g  = (const float*)d_in[15];
    const float* ln2b  = (const float*)d_in[16];
    const float* W1    = (const float*)d_in[17];
    const float* b1    = (const float*)d_in[18];
    const float* W2    = (const float*)d_in[19];
    const float* b2    = (const float*)d_in[20];
    float* out = (float*)d_out;

    float *X, *ATT, *P, *QKV, *bqkv;
    uint2 *X4, *ATT4, *H14, *QKVW4, *WO4, *W14, *W24;
    cudaGetSymbolAddress((void**)&X,    g_X);
    cudaGetSymbolAddress((void**)&ATT,  g_ATT);
    cudaGetSymbolAddress((void**)&P,    g_P);
    cudaGetSymbolAddress((void**)&QKV,  g_QKV);
    cudaGetSymbolAddress((void**)&bqkv, g_bqkv);
    cudaGetSymbolAddress((void**)&X4,   g_X4);
    cudaGetSymbolAddress((void**)&ATT4, g_ATT4);
    cudaGetSymbolAddress((void**)&H14,  g_H14);
    cudaGetSymbolAddress((void**)&QKVW4,g_QKVW4);
    cudaGetSymbolAddress((void**)&WO4,  g_WO4);
    cudaGetSymbolAddress((void**)&W14,  g_W14);
    cudaGetSymbolAddress((void**)&W24,  g_W24);

    cudaFuncSetAttribute(hmma_gemm<0>, cudaFuncAttributeMaxDynamicSharedMemorySize, GSMEM);
    cudaFuncSetAttribute(hmma_gemm<1>, cudaFuncAttributeMaxDynamicSharedMemorySize, GSMEM);
    cudaFuncSetAttribute(attn_kernel, cudaFuncAttributeMaxDynamicSharedMemorySize, ATTN_SMEM);

    // weight prep (every replay; ~50us)
    biascat_kernel<<<24, 256>>>(bq, bk, bv, bqkv);
    dim3 tb(32, 8);
    for (int l = 0; l < LL; l++) {
        size_t oW = (size_t)l * EE * EE, oW1 = (size_t)l * EE * FFN, oW2 = (size_t)l * FFN * EE;
        prepW_kernel<<<dim3(16, 16), tb>>>(Wq + oW, QKVW4 + (size_t)l * 1536 * EE,             EE, EE);
        prepW_kernel<<<dim3(16, 16), tb>>>(Wk + oW, QKVW4 + (size_t)l * 1536 * EE +  512 * EE, EE, EE);
        prepW_kernel<<<dim3(16, 16), tb>>>(Wv + oW, QKVW4 + (size_t)l * 1536 * EE + 1024 * EE, EE, EE);
        prepW_kernel<<<dim3(16, 16), tb>>>(Wo + oW, WO4 + (size_t)l * EE * EE, EE, EE);
        prepW_kernel<<<dim3(64, 16), tb>>>(W1 + oW1, W14 + (size_t)l * FFN * EE, EE, FFN);
        prepW_kernel<<<dim3(16, 64), tb>>>(W2 + oW2, W24 + (size_t)l * EE * FFN, FFN, EE);
    }

    embed_kernel<<<MM, 128>>>(seq, W_emb, b_emb, pos, X);

    dim3 gQKV(1536 / 128, MM / 128);
    dim3 gE(EE / 128, MM / 128);
    dim3 gF(FFN / 128, MM / 128);
    dim3 attnG(SS / 64, BB * HH);
    int nEl = MM * EE;

    for (int l = 0; l < LL; l++) {
        size_t oB = (size_t)l * EE, oB1 = (size_t)l * FFN;

        cvtA_kernel<<<nEl / 256, 256>>>(X, X4, nEl);
        hmma_gemm<0><<<gQKV, 256, GSMEM>>>(X4, QKVW4 + (size_t)l * 1536 * EE,
                                           bqkv + (size_t)l * 1536, QKV, 1536, 4 * EE);
        attn_kernel<<<attnG, 256, ATTN_SMEM>>>(QKV, mask, ATT);

        cvtA_kernel<<<nEl / 256, 256>>>(ATT, ATT4, nEl);
        hmma_gemm<0><<<gE, 256, GSMEM>>>(ATT4, WO4 + (size_t)l * EE * EE, bo + oB, P, EE, 4 * EE);
        ln_kernel<<<MM, 128>>>(X, P, ln1g + oB, ln1b + oB, X);

        cvtA_kernel<<<nEl / 256, 256>>>(X, X4, nEl);
        hmma_gemm<1><<<gF, 256, GSMEM>>>(X4, W14 + (size_t)l * FFN * EE, b1 + oB1, H14, FFN, 4 * EE);
        hmma_gemm<0><<<gE, 256, GSMEM>>>(H14, W24 + (size_t)l * EE * FFN, b2 + oB, P, EE, 4 * FFN);

        float* dst = (l == LL - 1) ? out : X;
        ln_kernel<<<MM, 128>>>(X, P, ln2g + oB, ln2b + oB, dst);
    }
}

// round 5
// speedup vs baseline: 2.6928x; 1.9416x over previous
#include <cuda_runtime.h>
#include <cuda_bf16.h>
#include <math.h>
#include <stdint.h>

#define BB 2
#define SS 2048
#define FF_IN 64
#define EE 512
#define HH 8
#define DH 64
#define LL 4
#define FFN 2048
#define MM (BB * SS)
#define ATTN_SCALE 0.044194173824159216f

// ---------------- helpers ----------------
__device__ __forceinline__ uint32_t smem_u32(const void* p) {
    uint32_t a;
    asm("{ .reg .u64 t; cvta.to.shared.u64 t, %1; cvt.u32.u64 %0, t; }" : "=r"(a) : "l"(p));
    return a;
}
#define SWZ128(o) ((o) ^ (((o) >> 3) & 0x70))

__device__ __forceinline__ void cp16(uint32_t s, const void* g) {
    asm volatile("cp.async.cg.shared.global [%0], [%1], 16;" :: "r"(s), "l"(g) : "memory");
}
#define CP_COMMIT() asm volatile("cp.async.commit_group;" ::: "memory")

__device__ __forceinline__ void ldsm4(uint32_t* d, uint32_t a) {
    asm volatile("ldmatrix.sync.aligned.m8n8.x4.shared.b16 {%0,%1,%2,%3}, [%4];"
                 : "=r"(d[0]), "=r"(d[1]), "=r"(d[2]), "=r"(d[3]) : "r"(a));
}
__device__ __forceinline__ void mma_bf16(float* c, const uint32_t* a, const uint32_t* b) {
    asm volatile("mma.sync.aligned.m16n8k16.row.col.f32.bf16.bf16.f32 "
        "{%0,%1,%2,%3}, {%4,%5,%6,%7}, {%8,%9}, {%0,%1,%2,%3};"
        : "+f"(c[0]), "+f"(c[1]), "+f"(c[2]), "+f"(c[3])
        : "r"(a[0]), "r"(a[1]), "r"(a[2]), "r"(a[3]), "r"(b[0]), "r"(b[1]));
}

// quad split (for linear GEMMs): A slots (ah,ah,al,al); B slots (bh,bl,bh,bl)
__device__ __forceinline__ uint2 quad_a(float f) {
    __nv_bfloat16 h = __float2bfloat16(f);
    __nv_bfloat16 l = __float2bfloat16(f - __bfloat162float(h));
    return make_uint2((uint32_t)__bfloat16_as_ushort(h) * 0x10001u,
                      (uint32_t)__bfloat16_as_ushort(l) * 0x10001u);
}
__device__ __forceinline__ uint2 quad_b(float f) {
    __nv_bfloat16 h = __float2bfloat16(f);
    __nv_bfloat16 l = __float2bfloat16(f - __bfloat162float(h));
    uint32_t w = (uint32_t)__bfloat16_as_ushort(h) | ((uint32_t)__bfloat16_as_ushort(l) << 16);
    return make_uint2(w, w);
}
// hi/lo split packers (for attention)
__device__ __forceinline__ void split_hl(float f, uint16_t& h, uint16_t& l) {
    __nv_bfloat16 hb = __float2bfloat16(f);
    __nv_bfloat16 lb = __float2bfloat16(f - __bfloat162float(hb));
    h = __bfloat16_as_ushort(hb); l = __bfloat16_as_ushort(lb);
}
__device__ __forceinline__ uint32_t pack2(uint16_t a, uint16_t b) {
    return (uint32_t)a | ((uint32_t)b << 16);
}

// ---------------- scratch ----------------
__device__ float g_X[MM * EE];
__device__ float g_P[MM * EE];
__device__ float g_Vf[MM * EE];
__device__ float g_bqkv[LL * 1536];
__device__ uint2 g_X4[MM * EE];
__device__ uint2 g_ATT4[MM * EE];
__device__ uint2 g_H14[MM * FFN];
__device__ __nv_bfloat16 g_Qh[MM * EE], g_Ql[MM * EE];
__device__ __nv_bfloat16 g_Kh[MM * EE], g_Kl[MM * EE];
__device__ __nv_bfloat16 g_VhT[BB * HH * DH * SS], g_VlT[BB * HH * DH * SS];
__device__ uint2 g_QKVW4[LL][1536 * EE];
__device__ uint2 g_WO4[LL][EE * EE];
__device__ uint2 g_W14[LL][FFN * EE];
__device__ uint2 g_W24[LL][EE * FFN];

// W[K][N] fp32 -> B4[N][K] quads
__global__ __launch_bounds__(256) void prepW_kernel(
    const float* __restrict__ W, uint2* __restrict__ B4, int K, int N)
{
    __shared__ uint2 t[32][33];
    int k0 = blockIdx.y * 32, n0 = blockIdx.x * 32;
    int tx = threadIdx.x, ty = threadIdx.y;
    #pragma unroll
    for (int i = 0; i < 4; i++)
        t[ty + i * 8][tx] = quad_b(W[(size_t)(k0 + ty + i * 8) * N + n0 + tx]);
    __syncthreads();
    #pragma unroll
    for (int i = 0; i < 4; i++)
        B4[(size_t)(n0 + ty + i * 8) * K + k0 + tx] = t[tx][ty + i * 8];
}

__global__ __launch_bounds__(256) void biascat_kernel(
    const float* __restrict__ bq, const float* __restrict__ bk,
    const float* __restrict__ bv, float* __restrict__ o)
{
    int i = blockIdx.x * 256 + threadIdx.x;
    if (i >= LL * 1536) return;
    int l = i / 1536, j = i - l * 1536;
    o[i] = (j < 512) ? bq[l * 512 + j] : (j < 1024) ? bk[l * 512 + j - 512] : bv[l * 512 + j - 1024];
}

// V fp32 [token][512] -> VhT/VlT [bh][d][s]
__global__ __launch_bounds__(256) void vprep_kernel(
    const float* __restrict__ Vf, __nv_bfloat16* __restrict__ VhT, __nv_bfloat16* __restrict__ VlT)
{
    __shared__ float t[64][65];
    int tt = blockIdx.x, hh = blockIdx.y;
    int b = (tt * 64) / SS, s0 = (tt * 64) % SS;
    int tx = threadIdx.x & 63, ty = threadIdx.x >> 6;
    #pragma unroll
    for (int i = 0; i < 16; i++) {
        int r = ty + i * 4;
        t[r][tx] = Vf[(size_t)(tt * 64 + r) * EE + hh * DH + tx];
    }
    __syncthreads();
    #pragma unroll
    for (int i = 0; i < 16; i++) {
        int d = ty + i * 4;
        float v = t[tx][d];
        uint16_t h, l; split_hl(v, h, l);
        size_t idx = ((size_t)(b * HH + hh) * DH + d) * SS + s0 + tx;
        VhT[idx] = __ushort_as_bfloat16(h);
        VlT[idx] = __ushort_as_bfloat16(l);
    }
}

// ---------------- HMMA GEMM (quad inputs) ----------------
// OUTQ: 0 = fp32+bias, 1 = relu+quad, 2 = QKV split (qh/ql/kh/kl bf16 + vf fp32)
#define GSMEM 65536
template <int OUTQ>
__global__ __launch_bounds__(256, 2) void hmma_gemm(
    const uint2* __restrict__ A4, const uint2* __restrict__ B4,
    const float* __restrict__ bias, void* __restrict__ Cout, int ldc, int K4,
    __nv_bfloat16* __restrict__ qh, __nv_bfloat16* __restrict__ ql,
    __nv_bfloat16* __restrict__ kh, __nv_bfloat16* __restrict__ kl,
    float* __restrict__ vf)
{
    extern __shared__ char smem[];
    const uint32_t sb = smem_u32(smem);
    const int tid = threadIdx.x, lane = tid & 31, wid = tid >> 5;
    const int wm = (wid >> 1) * 32, wn = (wid & 1) * 64;
    const int cRow = blockIdx.y * 128, cCol = blockIdx.x * 128;
    const size_t rowbytes = (size_t)K4 * 2;
    const char* Abase = (const char*)(A4 + (size_t)cRow * (K4 >> 2));
    const char* Bbase = (const char*)(B4 + (size_t)cCol * (K4 >> 2));

    float acc[2][8][4];
    #pragma unroll
    for (int a = 0; a < 2; a++)
        #pragma unroll
        for (int b = 0; b < 8; b++)
            #pragma unroll
            for (int c = 0; c < 4; c++) acc[a][b][c] = 0.f;

    const int lr = tid >> 3, lc = (tid & 7) * 16;
    auto load_stage = [&](int s) {
        uint32_t dA = sb + (s & 1) * 32768, dB = dA + 16384;
        size_t kb = (size_t)s * 128;
        #pragma unroll
        for (int i = 0; i < 4; i++) {
            int r = lr + i * 32;
            cp16(dA + SWZ128(r * 128 + lc), Abase + (size_t)r * rowbytes + kb + lc);
        }
        #pragma unroll
        for (int i = 0; i < 4; i++) {
            int r = lr + i * 32;
            cp16(dB + SWZ128(r * 128 + lc), Bbase + (size_t)r * rowbytes + kb + lc);
        }
    };

    const int NS = K4 / 64;
    load_stage(0); CP_COMMIT();
    for (int s = 0; s < NS; s++) {
        if (s + 1 < NS) {
            load_stage(s + 1); CP_COMMIT();
            asm volatile("cp.async.wait_group 1;" ::: "memory");
        } else {
            asm volatile("cp.async.wait_group 0;" ::: "memory");
        }
        __syncthreads();
        uint32_t sA = sb + (s & 1) * 32768, sB = sA + 16384;
        #pragma unroll
        for (int ks = 0; ks < 4; ks++) {
            int bc = ks * 32;
            uint32_t af[2][4], bf[4][4];
            #pragma unroll
            for (int mt = 0; mt < 2; mt++) {
                int row = wm + mt * 16 + ((lane >> 3) & 1) * 8 + (lane & 7);
                int col = bc + (lane >> 4) * 16;
                ldsm4(af[mt], sA + SWZ128(row * 128 + col));
            }
            #pragma unroll
            for (int p = 0; p < 4; p++) {
                int row = wn + p * 16 + ((lane >> 4) & 1) * 8 + (lane & 7);
                int col = bc + ((lane >> 3) & 1) * 16;
                ldsm4(bf[p], sB + SWZ128(row * 128 + col));
            }
            #pragma unroll
            for (int mt = 0; mt < 2; mt++)
                #pragma unroll
                for (int nt = 0; nt < 8; nt++)
                    mma_bf16(acc[mt][nt], af[mt], &bf[nt >> 1][(nt & 1) * 2]);
        }
        __syncthreads();
    }

    #pragma unroll
    for (int mt = 0; mt < 2; mt++)
        #pragma unroll
        for (int rp = 0; rp < 2; rp++) {
            int row = cRow + wm + mt * 16 + rp * 8 + (lane >> 2);
            #pragma unroll
            for (int nt = 0; nt < 8; nt++) {
                int col = cCol + wn + nt * 8 + (lane & 3) * 2;
                float2 bz = *(const float2*)(bias + col);
                float v0 = acc[mt][nt][rp * 2]     + bz.x;
                float v1 = acc[mt][nt][rp * 2 + 1] + bz.y;
                if (OUTQ == 1) {
                    v0 = fmaxf(v0, 0.f); v1 = fmaxf(v1, 0.f);
                    uint2 q0 = quad_a(v0), q1 = quad_a(v1);
                    *(uint4*)((uint2*)Cout + (size_t)row * ldc + col) =
                        make_uint4(q0.x, q0.y, q1.x, q1.y);
                } else if (OUTQ == 2) {
                    if (col < 512) {
                        float s0 = v0 * ATTN_SCALE, s1 = v1 * ATTN_SCALE;
                        uint16_t h0, l0, h1, l1;
                        split_hl(s0, h0, l0); split_hl(s1, h1, l1);
                        *(uint32_t*)(qh + (size_t)row * EE + col) = pack2(h0, h1);
                        *(uint32_t*)(ql + (size_t)row * EE + col) = pack2(l0, l1);
                    } else if (col < 1024) {
                        int c = col - 512;
                        uint16_t h0, l0, h1, l1;
                        split_hl(v0, h0, l0); split_hl(v1, h1, l1);
                        *(uint32_t*)(kh + (size_t)row * EE + c) = pack2(h0, h1);
                        *(uint32_t*)(kl + (size_t)row * EE + c) = pack2(l0, l1);
                    } else {
                        *(float2*)(vf + (size_t)row * EE + col - 1024) = make_float2(v0, v1);
                    }
                } else {
                    *(float2*)((float*)Cout + (size_t)row * ldc + col) = make_float2(v0, v1);
                }
            }
        }
}

// ---------------- HMMA flash attention ----------------
// CTA: 128 queries x one (b,h). 64-key tiles, hi/lo 3-term split both matmuls.
// smem: Qh 0, Ql 16384, stages at 32768+st*32768 {Kh,Kl,Vh,Vl each 8192}, Ms at 98304
#define ATTN_SMEM2 (98304 + 512)
__global__ __launch_bounds__(256) void attn_hmma(
    const __nv_bfloat16* __restrict__ Qh, const __nv_bfloat16* __restrict__ Ql,
    const __nv_bfloat16* __restrict__ Kh, const __nv_bfloat16* __restrict__ Kl,
    const __nv_bfloat16* __restrict__ VhT, const __nv_bfloat16* __restrict__ VlT,
    const int* __restrict__ mask, uint2* __restrict__ ATT4)
{
    extern __shared__ char smem[];
    const uint32_t sb = smem_u32(smem);
    int* Ms = (int*)(smem + 98304);
    const int tid = threadIdx.x, lane = tid & 31, wid = tid >> 5;
    const int bh = blockIdx.y, b = bh >> 3, h = bh & 7;
    const int qrow0 = blockIdx.x * 128;
    const int wr = wid * 16;

    // Q tiles (persist)
    {
        const char* qhp = (const char*)(Qh + (size_t)(b * SS + qrow0) * EE + h * DH);
        const char* qlp = (const char*)(Ql + (size_t)(b * SS + qrow0) * EE + h * DH);
        #pragma unroll
        for (int i = 0; i < 4; i++) {
            int id = tid + i * 256;
            int r = id >> 3, ck = (id & 7) * 16;
            cp16(sb +         SWZ128(r * 128 + ck), qhp + (size_t)r * 1024 + ck);
            cp16(sb + 16384 + SWZ128(r * 128 + ck), qlp + (size_t)r * 1024 + ck);
        }
    }
    auto load_stage = [&](int kt) {
        uint32_t st = sb + 32768 + (kt & 1) * 32768;
        const char* khp = (const char*)(Kh + (size_t)(b * SS + kt * 64) * EE + h * DH);
        const char* klp = (const char*)(Kl + (size_t)(b * SS + kt * 64) * EE + h * DH);
        const char* vhp = (const char*)(VhT + (size_t)bh * DH * SS + kt * 64);
        const char* vlp = (const char*)(VlT + (size_t)bh * DH * SS + kt * 64);
        #pragma unroll
        for (int i = 0; i < 2; i++) {
            int id = tid + i * 256;
            int r = id >> 3, ck = (id & 7) * 16;
            cp16(st +         SWZ128(r * 128 + ck), khp + (size_t)r * 1024 + ck);
            cp16(st + 8192  + SWZ128(r * 128 + ck), klp + (size_t)r * 1024 + ck);
            cp16(st + 16384 + SWZ128(r * 128 + ck), vhp + (size_t)r * (SS * 2) + ck);
            cp16(st + 24576 + SWZ128(r * 128 + ck), vlp + (size_t)r * (SS * 2) + ck);
        }
        if (tid < 64) Ms[(kt & 1) * 64 + tid] = mask[b * SS + kt * 64 + tid];
    };

    float m_i[2] = {-INFINITY, -INFINITY}, l_i[2] = {0.f, 0.f};
    float o_acc[8][4];
    #pragma unroll
    for (int nt = 0; nt < 8; nt++)
        #pragma unroll
        for (int c = 0; c < 4; c++) o_acc[nt][c] = 0.f;

    load_stage(0); CP_COMMIT();
    const int NT = SS / 64;
    for (int kt = 0; kt < NT; kt++) {
        if (kt + 1 < NT) {
            load_stage(kt + 1); CP_COMMIT();
            asm volatile("cp.async.wait_group 1;" ::: "memory");
        } else {
            asm volatile("cp.async.wait_group 0;" ::: "memory");
        }
        __syncthreads();
        const uint32_t st = sb + 32768 + (kt & 1) * 32768;
        const uint32_t sKh = st, sKl = st + 8192, sVh = st + 16384, sVl = st + 24576;

        // S = Q K^T (3-term split)
        float s_acc[8][4];
        #pragma unroll
        for (int nt = 0; nt < 8; nt++)
            #pragma unroll
            for (int c = 0; c < 4; c++) s_acc[nt][c] = 0.f;

        #pragma unroll
        for (int kc = 0; kc < 4; kc++) {
            int bc = kc * 32;
            uint32_t qhf[4], qlf[4];
            {
                int row = wr + ((lane >> 3) & 1) * 8 + (lane & 7);
                int col = bc + (lane >> 4) * 16;
                ldsm4(qhf, sb +         SWZ128(row * 128 + col));
                ldsm4(qlf, sb + 16384 + SWZ128(row * 128 + col));
            }
            #pragma unroll
            for (int ng = 0; ng < 4; ng++) {
                uint32_t khf[4], klf[4];
                int row = ng * 16 + ((lane >> 4) & 1) * 8 + (lane & 7);
                int col = bc + ((lane >> 3) & 1) * 16;
                ldsm4(khf, sKh + SWZ128(row * 128 + col));
                ldsm4(klf, sKl + SWZ128(row * 128 + col));
                #pragma unroll
                for (int t2 = 0; t2 < 2; t2++) {
                    int nt = ng * 2 + t2;
                    mma_bf16(s_acc[nt], qhf, &khf[t2 * 2]);
                    mma_bf16(s_acc[nt], qhf, &klf[t2 * 2]);
                    mma_bf16(s_acc[nt], qlf, &khf[t2 * 2]);
                }
            }
        }

        // mask
        const int t4 = (lane & 3) * 2;
        const int msb = (kt & 1) * 64;
        #pragma unroll
        for (int nt = 0; nt < 8; nt++) {
            if (Ms[msb + nt * 8 + t4] == 0)     { s_acc[nt][0] = -1e20f; s_acc[nt][2] = -1e20f; }
            if (Ms[msb + nt * 8 + t4 + 1] == 0) { s_acc[nt][1] = -1e20f; s_acc[nt][3] = -1e20f; }
        }

        // online softmax (rows r=0 -> c0,c1; r=1 -> c2,c3)
        #pragma unroll
        for (int r = 0; r < 2; r++) {
            float mx = -INFINITY;
            #pragma unroll
            for (int nt = 0; nt < 8; nt++)
                mx = fmaxf(mx, fmaxf(s_acc[nt][r * 2], s_acc[nt][r * 2 + 1]));
            mx = fmaxf(mx, __shfl_xor_sync(0xffffffffu, mx, 1));
            mx = fmaxf(mx, __shfl_xor_sync(0xffffffffu, mx, 2));
            float mnew = fmaxf(m_i[r], mx);
            float corr = __expf(m_i[r] - mnew);
            float rs = 0.f;
            #pragma unroll
            for (int nt = 0; nt < 8; nt++) {
                float p0 = __expf(s_acc[nt][r * 2] - mnew);
                float p1 = __expf(s_acc[nt][r * 2 + 1] - mnew);
                s_acc[nt][r * 2] = p0; s_acc[nt][r * 2 + 1] = p1;
                rs += p0 + p1;
            }
            rs += __shfl_xor_sync(0xffffffffu, rs, 1);
            rs += __shfl_xor_sync(0xffffffffu, rs, 2);
            l_i[r] = l_i[r] * corr + rs;
            m_i[r] = mnew;
            #pragma unroll
            for (int nt = 0; nt < 8; nt++) {
                o_acc[nt][r * 2] *= corr; o_acc[nt][r * 2 + 1] *= corr;
            }
        }

        // O += P V (P fragments built in registers; 3-term split)
        #pragma unroll
        for (int kc = 0; kc < 4; kc++) {
            uint32_t ph[4], pl[4];
            {
                uint16_t h0, l0, h1, l1;
                split_hl(s_acc[2 * kc][0], h0, l0); split_hl(s_acc[2 * kc][1], h1, l1);
                ph[0] = pack2(h0, h1); pl[0] = pack2(l0, l1);
                split_hl(s_acc[2 * kc][2], h0, l0); split_hl(s_acc[2 * kc][3], h1, l1);
                ph[1] = pack2(h0, h1); pl[1] = pack2(l0, l1);
                split_hl(s_acc[2 * kc + 1][0], h0, l0); split_hl(s_acc[2 * kc + 1][1], h1, l1);
                ph[2] = pack2(h0, h1); pl[2] = pack2(l0, l1);
                split_hl(s_acc[2 * kc + 1][2], h0, l0); split_hl(s_acc[2 * kc + 1][3], h1, l1);
                ph[3] = pack2(h0, h1); pl[3] = pack2(l0, l1);
            }
            #pragma unroll
            for (int ng = 0; ng < 4; ng++) {
                uint32_t vhf[4], vlf[4];
                int row = ng * 16 + ((lane >> 4) & 1) * 8 + (lane & 7);
                int col = kc * 32 + ((lane >> 3) & 1) * 16;
                ldsm4(vhf, sVh + SWZ128(row * 128 + col));
                ldsm4(vlf, sVl + SWZ128(row * 128 + col));
                #pragma unroll
                for (int t2 = 0; t2 < 2; t2++) {
                    int nt = ng * 2 + t2;
                    mma_bf16(o_acc[nt], ph, &vhf[t2 * 2]);
                    mma_bf16(o_acc[nt], ph, &vlf[t2 * 2]);
                    mma_bf16(o_acc[nt], pl, &vhf[t2 * 2]);
                }
            }
        }
        __syncthreads();
    }

    // epilogue: write ATT4 quads
    const int g = lane >> 2;
    #pragma unroll
    for (int r = 0; r < 2; r++) {
        float inv = 1.f / l_i[r];
        int row = qrow0 + wr + g + r * 8;
        #pragma unroll
        for (int nt = 0; nt < 8; nt++) {
            int d = nt * 8 + (lane & 3) * 2;
            float v0 = o_acc[nt][r * 2] * inv, v1 = o_acc[nt][r * 2 + 1] * inv;
            uint2 q0 = quad_a(v0), q1 = quad_a(v1);
            *(uint4*)(ATT4 + (size_t)(b * SS + row) * EE + h * DH + d) =
                make_uint4(q0.x, q0.y, q1.x, q1.y);
        }
    }
}

// ---------------- embedding (writes X + X4) ----------------
__global__ __launch_bounds__(128) void embed_kernel(
    const float* __restrict__ seq, const float* __restrict__ W,
    const float* __restrict__ bias, const float* __restrict__ pos,
    float* __restrict__ X, uint2* __restrict__ X4)
{
    int m = blockIdx.x, s = m & (SS - 1), tid = threadIdx.x;
    __shared__ float srow[FF_IN];
    if (tid < FF_IN) srow[tid] = seq[(size_t)m * FF_IN + tid];
    __syncthreads();
    int n = tid * 4;
    float4 acc = *(const float4*)(bias + n);
    float4 pv  = *(const float4*)(pos + (size_t)s * EE + n);
    acc.x += pv.x; acc.y += pv.y; acc.z += pv.z; acc.w += pv.w;
    #pragma unroll 8
    for (int f = 0; f < FF_IN; f++) {
        float sv = srow[f];
        float4 w = *(const float4*)(W + (size_t)f * EE + n);
        acc.x += sv * w.x; acc.y += sv * w.y; acc.z += sv * w.z; acc.w += sv * w.w;
    }
    *(float4*)(X + (size_t)m * EE + n) = acc;
    uint2 q0 = quad_a(acc.x), q1 = quad_a(acc.y), q2 = quad_a(acc.z), q3 = quad_a(acc.w);
    uint2* xp = X4 + (size_t)m * EE + n;
    *(uint4*)xp       = make_uint4(q0.x, q0.y, q1.x, q1.y);
    *(uint4*)(xp + 2) = make_uint4(q2.x, q2.y, q3.x, q3.y);
}

// ---------------- residual + LN (optional quad out) ----------------
__global__ __launch_bounds__(128) void ln_kernel(
    const float* __restrict__ a, const float* __restrict__ br,
    const float* __restrict__ g, const float* __restrict__ be,
    float* __restrict__ out, uint2* __restrict__ x4)
{
    int m = blockIdx.x, tid = threadIdx.x;
    size_t base = (size_t)m * EE + tid * 4;
    float4 va = *(const float4*)(a + base);
    float4 vb = *(const float4*)(br + base);
    float x0 = va.x + vb.x, x1 = va.y + vb.y, x2 = va.z + vb.z, x3 = va.w + vb.w;
    float s = x0 + x1 + x2 + x3;
    float ss = x0 * x0 + x1 * x1 + x2 * x2 + x3 * x3;
    #pragma unroll
    for (int off = 16; off; off >>= 1) {
        s  += __shfl_xor_sync(0xffffffffu, s, off);
        ss += __shfl_xor_sync(0xffffffffu, ss, off);
    }
    __shared__ float red[8];
    int w = tid >> 5;
    if ((tid & 31) == 0) { red[w] = s; red[4 + w] = ss; }
    __syncthreads();
    s  = red[0] + red[1] + red[2] + red[3];
    ss = red[4] + red[5] + red[6] + red[7];
    float mean = s * (1.f / EE);
    float var  = ss * (1.f / EE) - mean * mean;
    float r = rsqrtf(var + 1e-5f);
    float4 gg = *(const float4*)(g + tid * 4);
    float4 bb = *(const float4*)(be + tid * 4);
    float4 o;
    o.x = (x0 - mean) * r * gg.x + bb.x;
    o.y = (x1 - mean) * r * gg.y + bb.y;
    o.z = (x2 - mean) * r * gg.z + bb.z;
    o.w = (x3 - mean) * r * gg.w + bb.w;
    *(float4*)(out + base) = o;
    if (x4) {
        uint2 q0 = quad_a(o.x), q1 = quad_a(o.y), q2 = quad_a(o.z), q3 = quad_a(o.w);
        uint2* xp = x4 + base;
        *(uint4*)xp       = make_uint4(q0.x, q0.y, q1.x, q1.y);
        *(uint4*)(xp + 2) = make_uint4(q2.x, q2.y, q3.x, q3.y);
    }
}

// ---------------- launch ----------------
extern "C" void kernel_launch(void* const* d_in, const int* in_sizes, int n_in,
                              void* d_out, int out_size)
{
    const float* seq   = (const float*)d_in[0];
    const int*   mask  = (const int*)  d_in[1];
    const float* W_emb = (const float*)d_in[2];
    const float* b_emb = (const float*)d_in[3];
    const float* pos   = (const float*)d_in[4];
    const float* Wq    = (const float*)d_in[5];
    const float* bq    = (const float*)d_in[6];
    const float* Wk    = (const float*)d_in[7];
    const float* bk    = (const float*)d_in[8];
    const float* Wv    = (const float*)d_in[9];
    const float* bv    = (const float*)d_in[10];
    const float* Wo    = (const float*)d_in[11];
    const float* bo    = (const float*)d_in[12];
    const float* ln1g  = (const float*)d_in[13];
    const float* ln1b  = (const float*)d_in[14];
    const float* ln2g  = (const float*)d_in[15];
    const float* ln2b  = (const float*)d_in[16];
    const float* W1    = (const float*)d_in[17];
    const float* b1    = (const float*)d_in[18];
    const float* W2    = (const float*)d_in[19];
    const float* b2    = (const float*)d_in[20];
    float* out = (float*)d_out;

    float *X, *P, *Vf, *bqkv;
    uint2 *X4, *ATT4, *H14, *QKVW4, *WO4, *W14, *W24;
    __nv_bfloat16 *Qh, *Ql, *Kh, *Kl, *VhT, *VlT;
    cudaGetSymbolAddress((void**)&X,    g_X);
    cudaGetSymbolAddress((void**)&P,    g_P);
    cudaGetSymbolAddress((void**)&Vf,   g_Vf);
    cudaGetSymbolAddress((void**)&bqkv, g_bqkv);
    cudaGetSymbolAddress((void**)&X4,   g_X4);
    cudaGetSymbolAddress((void**)&ATT4, g_ATT4);
    cudaGetSymbolAddress((void**)&H14,  g_H14);
    cudaGetSymbolAddress((void**)&QKVW4,g_QKVW4);
    cudaGetSymbolAddress((void**)&WO4,  g_WO4);
    cudaGetSymbolAddress((void**)&W14,  g_W14);
    cudaGetSymbolAddress((void**)&W24,  g_W24);
    cudaGetSymbolAddress((void**)&Qh,   g_Qh);
    cudaGetSymbolAddress((void**)&Ql,   g_Ql);
    cudaGetSymbolAddress((void**)&Kh,   g_Kh);
    cudaGetSymbolAddress((void**)&Kl,   g_Kl);
    cudaGetSymbolAddress((void**)&VhT,  g_VhT);
    cudaGetSymbolAddress((void**)&VlT,  g_VlT);

    cudaFuncSetAttribute(hmma_gemm<0>, cudaFuncAttributeMaxDynamicSharedMemorySize, GSMEM);
    cudaFuncSetAttribute(hmma_gemm<1>, cudaFuncAttributeMaxDynamicSharedMemorySize, GSMEM);
    cudaFuncSetAttribute(hmma_gemm<2>, cudaFuncAttributeMaxDynamicSharedMemorySize, GSMEM);
    cudaFuncSetAttribute(attn_hmma, cudaFuncAttributeMaxDynamicSharedMemorySize, ATTN_SMEM2);

    biascat_kernel<<<24, 256>>>(bq, bk, bv, bqkv);
    dim3 tb(32, 8);
    for (int l = 0; l < LL; l++) {
        size_t oW = (size_t)l * EE * EE, oW1 = (size_t)l * EE * FFN, oW2 = (size_t)l * FFN * EE;
        prepW_kernel<<<dim3(16, 16), tb>>>(Wq + oW, QKVW4 + (size_t)l * 1536 * EE,             EE, EE);
        prepW_kernel<<<dim3(16, 16), tb>>>(Wk + oW, QKVW4 + (size_t)l * 1536 * EE +  512 * EE, EE, EE);
        prepW_kernel<<<dim3(16, 16), tb>>>(Wv + oW, QKVW4 + (size_t)l * 1536 * EE + 1024 * EE, EE, EE);
        prepW_kernel<<<dim3(16, 16), tb>>>(Wo + oW, WO4 + (size_t)l * EE * EE, EE, EE);
        prepW_kernel<<<dim3(64, 16), tb>>>(W1 + oW1, W14 + (size_t)l * FFN * EE, EE, FFN);
        prepW_kernel<<<dim3(16, 64), tb>>>(W2 + oW2, W24 + (size_t)l * EE * FFN, FFN, EE);
    }

    embed_kernel<<<MM, 128>>>(seq, W_emb, b_emb, pos, X, X4);

    dim3 gQKV(1536 / 128, MM / 128);
    dim3 gE(EE / 128, MM / 128);
    dim3 gF(FFN / 128, MM / 128);
    dim3 attnG(SS / 128, BB * HH);

    for (int l = 0; l < LL; l++) {
        size_t oB = (size_t)l * EE, oB1 = (size_t)l * FFN;

        hmma_gemm<2><<<gQKV, 256, GSMEM>>>(X4, QKVW4 + (size_t)l * 1536 * EE,
                                           bqkv + (size_t)l * 1536, nullptr, 0, 4 * EE,
                                           Qh, Ql, Kh, Kl, Vf);
        vprep_kernel<<<dim3(MM / 64, HH), 256>>>(Vf, VhT, VlT);
        attn_hmma<<<attnG, 256, ATTN_SMEM2>>>(Qh, Ql, Kh, Kl, VhT, VlT, mask, ATT4);

        hmma_gemm<0><<<gE, 256, GSMEM>>>(ATT4, WO4 + (size_t)l * EE * EE, bo + oB, P, EE, 4 * EE,
                                         nullptr, nullptr, nullptr, nullptr, nullptr);
        ln_kernel<<<MM, 128>>>(X, P, ln1g + oB, ln1b + oB, X, X4);

        hmma_gemm<1><<<gF, 256, GSMEM>>>(X4, W14 + (size_t)l * FFN * EE, b1 + oB1, H14, FFN, 4 * EE,
                                         nullptr, nullptr, nullptr, nullptr, nullptr);
        hmma_gemm<0><<<gE, 256, GSMEM>>>(H14, W24 + (size_t)l * EE * FFN, b2 + oB, P, EE, 4 * FFN,
                                         nullptr, nullptr, nullptr, nullptr, nullptr);

        float* dst = (l == LL - 1) ? out : X;
        ln_kernel<<<MM, 128>>>(X, P, ln2g + oB, ln2b + oB, dst, (l == LL - 1) ? nullptr : X4);
    }
}

// round 6
// speedup vs baseline: 3.2803x; 1.2182x over previous
#include <cuda_runtime.h>
#include <cuda_bf16.h>
#include <math.h>
#include <stdint.h>

#define BB 2
#define SS 2048
#define FF_IN 64
#define EE 512
#define HH 8
#define DH 64
#define LL 4
#define FFN 2048
#define MM (BB * SS)
#define ATTN_SCALE 0.044194173824159216f

// ---------------- helpers ----------------
__device__ __forceinline__ uint32_t smem_u32(const void* p) {
    uint32_t a;
    asm("{ .reg .u64 t; cvta.to.shared.u64 t, %1; cvt.u32.u64 %0, t; }" : "=r"(a) : "l"(p));
    return a;
}
#define SWZ128(o) ((o) ^ (((o) >> 3) & 0x70))

__device__ __forceinline__ void cp16(uint32_t s, const void* g) {
    asm volatile("cp.async.cg.shared.global [%0], [%1], 16;" :: "r"(s), "l"(g) : "memory");
}
#define CP_COMMIT() asm volatile("cp.async.commit_group;" ::: "memory")

__device__ __forceinline__ void ldsm4(uint32_t* d, uint32_t a) {
    asm volatile("ldmatrix.sync.aligned.m8n8.x4.shared.b16 {%0,%1,%2,%3}, [%4];"
                 : "=r"(d[0]), "=r"(d[1]), "=r"(d[2]), "=r"(d[3]) : "r"(a));
}
__device__ __forceinline__ void mma_bf16(float* c, const uint32_t* a, const uint32_t* b) {
    asm volatile("mma.sync.aligned.m16n8k16.row.col.f32.bf16.bf16.f32 "
        "{%0,%1,%2,%3}, {%4,%5,%6,%7}, {%8,%9}, {%0,%1,%2,%3};"
        : "+f"(c[0]), "+f"(c[1]), "+f"(c[2]), "+f"(c[3])
        : "r"(a[0]), "r"(a[1]), "r"(a[2]), "r"(a[3]), "r"(b[0]), "r"(b[1]));
}

__device__ __forceinline__ void split_hl(float f, uint16_t& h, uint16_t& l) {
    __nv_bfloat16 hb = __float2bfloat16(f);
    __nv_bfloat16 lb = __float2bfloat16(f - __bfloat162float(hb));
    h = __bfloat16_as_ushort(hb); l = __bfloat16_as_ushort(lb);
}
__device__ __forceinline__ uint32_t pack2(uint16_t a, uint16_t b) {
    return (uint32_t)a | ((uint32_t)b << 16);
}
// store 4 consecutive logical-k values (col % 4 == 0) into an HL row
__device__ __forceinline__ void store_hl4(__nv_bfloat16* rowp, int col,
                                          float v0, float v1, float v2, float v3) {
    int b = col >> 5, w = col & 31;
    uint16_t h0,l0,h1,l1,h2,l2,h3,l3;
    split_hl(v0,h0,l0); split_hl(v1,h1,l1); split_hl(v2,h2,l2); split_hl(v3,h3,l3);
    *(uint2*)(rowp + b*64 + w)      = make_uint2(pack2(h0,h1), pack2(h2,h3));
    *(uint2*)(rowp + b*64 + 32 + w) = make_uint2(pack2(l0,l1), pack2(l2,l3));
}
// store 2 consecutive (col % 2 == 0)
__device__ __forceinline__ void store_hl2(__nv_bfloat16* rowp, int col, float v0, float v1) {
    int b = col >> 5, w = col & 31;
    uint16_t h0,l0,h1,l1;
    split_hl(v0,h0,l0); split_hl(v1,h1,l1);
    *(uint32_t*)(rowp + b*64 + w)      = pack2(h0,h1);
    *(uint32_t*)(rowp + b*64 + 32 + w) = pack2(l0,l1);
}

// ---------------- scratch ----------------
// HL layout: row = logical K values as K/32 blocks of 128B (32 hi bf16 | 32 lo bf16)
__device__ float g_X[MM * EE];
__device__ float g_P[MM * EE];
__device__ float g_Vf[MM * EE];
__device__ float g_bqkv[LL * 1536];
__device__ __nv_bfloat16 g_XHL[MM * 2 * EE];
__device__ __nv_bfloat16 g_ATTHL[MM * 2 * EE];
__device__ __nv_bfloat16 g_H1HL[MM * 2 * FFN];
__device__ __nv_bfloat16 g_Qh[MM * EE], g_Ql[MM * EE];
__device__ __nv_bfloat16 g_Kh[MM * EE], g_Kl[MM * EE];
__device__ __nv_bfloat16 g_VhT[BB * HH * DH * SS], g_VlT[BB * HH * DH * SS];
__device__ __nv_bfloat16 g_QKVWHL[LL * 1536 * 2 * EE];
__device__ __nv_bfloat16 g_WOHL[LL * EE * 2 * EE];
__device__ __nv_bfloat16 g_W1HL[LL * FFN * 2 * EE];
__device__ __nv_bfloat16 g_W2HL[LL * EE * 2 * FFN];

// W[K][N] fp32 -> WHL[N][2K] hi/lo blocks. blockIdx.z = layer.
__global__ __launch_bounds__(256) void prepW_kernel(
    const float* __restrict__ W, __nv_bfloat16* __restrict__ D,
    int K, int N, size_t srcStride, size_t dstStride)
{
    __shared__ float t[32][33];
    W += (size_t)blockIdx.z * srcStride;
    D += (size_t)blockIdx.z * dstStride;
    int k0 = blockIdx.y * 32, n0 = blockIdx.x * 32;
    int tx = threadIdx.x, ty = threadIdx.y;
    #pragma unroll
    for (int i = 0; i < 4; i++)
        t[ty + i * 8][tx] = W[(size_t)(k0 + ty + i * 8) * N + n0 + tx];
    __syncthreads();
    int bofs = (k0 >> 5) * 64;
    #pragma unroll
    for (int i = 0; i < 4; i++) {
        int n = n0 + ty + i * 8;
        float v = t[tx][ty + i * 8];
        uint16_t h, l; split_hl(v, h, l);
        __nv_bfloat16* rp = D + (size_t)n * 2 * K + bofs;
        *(uint16_t*)(rp + tx)      = h;
        *(uint16_t*)(rp + 32 + tx) = l;
    }
}

__global__ __launch_bounds__(256) void biascat_kernel(
    const float* __restrict__ bq, const float* __restrict__ bk,
    const float* __restrict__ bv, float* __restrict__ o)
{
    int i = blockIdx.x * 256 + threadIdx.x;
    if (i >= LL * 1536) return;
    int l = i / 1536, j = i - l * 1536;
    o[i] = (j < 512) ? bq[l * 512 + j] : (j < 1024) ? bk[l * 512 + j - 512] : bv[l * 512 + j - 1024];
}

// V fp32 [token][512] -> VhT/VlT [bh][d][s]
__global__ __launch_bounds__(256) void vprep_kernel(
    const float* __restrict__ Vf, __nv_bfloat16* __restrict__ VhT, __nv_bfloat16* __restrict__ VlT)
{
    __shared__ float t[64][65];
    int tt = blockIdx.x, hh = blockIdx.y;
    int b = (tt * 64) / SS, s0 = (tt * 64) % SS;
    int tx = threadIdx.x & 63, ty = threadIdx.x >> 6;
    #pragma unroll
    for (int i = 0; i < 16; i++) {
        int r = ty + i * 4;
        t[r][tx] = Vf[(size_t)(tt * 64 + r) * EE + hh * DH + tx];
    }
    __syncthreads();
    #pragma unroll
    for (int i = 0; i < 16; i++) {
        int d = ty + i * 4;
        float v = t[tx][d];
        uint16_t h, l; split_hl(v, h, l);
        size_t idx = ((size_t)(b * HH + hh) * DH + d) * SS + s0 + tx;
        VhT[idx] = __ushort_as_bfloat16(h);
        VlT[idx] = __ushort_as_bfloat16(l);
    }
}

// ---------------- HL HMMA GEMM ----------------
// C[M,N] = A_HL[M,K] x B_HL[N,K] + bias (3-term hi/lo). Tile 128x128, stage = 32 logical k.
// OUTQ: 0 = fp32, 1 = relu + HL out, 2 = QKV split
#define GSMEM 65536
template <int OUTQ>
__global__ __launch_bounds__(256, 2) void hl_gemm(
    const __nv_bfloat16* __restrict__ A, const __nv_bfloat16* __restrict__ B,
    const float* __restrict__ bias, void* __restrict__ Cout, int ldc, int K,
    __nv_bfloat16* __restrict__ qh, __nv_bfloat16* __restrict__ ql,
    __nv_bfloat16* __restrict__ kh, __nv_bfloat16* __restrict__ kl,
    float* __restrict__ vf)
{
    extern __shared__ char smem[];
    const uint32_t sb = smem_u32(smem);
    const int tid = threadIdx.x, lane = tid & 31, wid = tid >> 5;
    const int wm = (wid >> 1) * 32, wn = (wid & 1) * 64;
    const int cRow = blockIdx.y * 128, cCol = blockIdx.x * 128;
    const size_t rowbytes = (size_t)K * 4;   // 2K bf16
    const char* Abase = (const char*)(A + (size_t)cRow * 2 * K);
    const char* Bbase = (const char*)(B + (size_t)cCol * 2 * K);

    float acc[2][8][4];
    #pragma unroll
    for (int a = 0; a < 2; a++)
        #pragma unroll
        for (int b = 0; b < 8; b++)
            #pragma unroll
            for (int c = 0; c < 4; c++) acc[a][b][c] = 0.f;

    const int lr = tid >> 3, lc = (tid & 7) * 16;
    auto load_stage = [&](int s) {
        uint32_t dA = sb + (s & 1) * 32768, dB = dA + 16384;
        size_t kb = (size_t)s * 128;
        #pragma unroll
        for (int i = 0; i < 4; i++) {
            int r = lr + i * 32;
            cp16(dA + SWZ128(r * 128 + lc), Abase + (size_t)r * rowbytes + kb + lc);
        }
        #pragma unroll
        for (int i = 0; i < 4; i++) {
            int r = lr + i * 32;
            cp16(dB + SWZ128(r * 128 + lc), Bbase + (size_t)r * rowbytes + kb + lc);
        }
    };

    const int NS = K / 32;
    load_stage(0); CP_COMMIT();
    for (int s = 0; s < NS; s++) {
        if (s + 1 < NS) {
            load_stage(s + 1); CP_COMMIT();
            asm volatile("cp.async.wait_group 1;" ::: "memory");
        } else {
            asm volatile("cp.async.wait_group 0;" ::: "memory");
        }
        __syncthreads();
        uint32_t sA = sb + (s & 1) * 32768, sB = sA + 16384;
        #pragma unroll
        for (int c = 0; c < 2; c++) {
            const int ch = c * 32, cl = 64 + c * 32;   // byte cols: hi, lo
            uint32_t ah[2][4], al[2][4];
            #pragma unroll
            for (int mt = 0; mt < 2; mt++) {
                int row = wm + mt * 16 + ((lane >> 3) & 1) * 8 + (lane & 7);
                int cq = (lane >> 4) * 16;
                ldsm4(ah[mt], sA + SWZ128(row * 128 + ch + cq));
                ldsm4(al[mt], sA + SWZ128(row * 128 + cl + cq));
            }
            #pragma unroll
            for (int ng = 0; ng < 4; ng++) {
                uint32_t bh[4], bl[4];
                int row = wn + ng * 16 + ((lane >> 4) & 1) * 8 + (lane & 7);
                int cq = ((lane >> 3) & 1) * 16;
                ldsm4(bh, sB + SWZ128(row * 128 + ch + cq));
                ldsm4(bl, sB + SWZ128(row * 128 + cl + cq));
                #pragma unroll
                for (int t2 = 0; t2 < 2; t2++) {
                    int nt = ng * 2 + t2;
                    #pragma unroll
                    for (int mt = 0; mt < 2; mt++) {
                        mma_bf16(acc[mt][nt], ah[mt], &bh[t2 * 2]);
                        mma_bf16(acc[mt][nt], ah[mt], &bl[t2 * 2]);
                        mma_bf16(acc[mt][nt], al[mt], &bh[t2 * 2]);
                    }
                }
            }
        }
        __syncthreads();
    }

    #pragma unroll
    for (int mt = 0; mt < 2; mt++)
        #pragma unroll
        for (int rp = 0; rp < 2; rp++) {
            int row = cRow + wm + mt * 16 + rp * 8 + (lane >> 2);
            #pragma unroll
            for (int nt = 0; nt < 8; nt++) {
                int col = cCol + wn + nt * 8 + (lane & 3) * 2;
                float2 bz = *(const float2*)(bias + col);
                float v0 = acc[mt][nt][rp * 2]     + bz.x;
                float v1 = acc[mt][nt][rp * 2 + 1] + bz.y;
                if (OUTQ == 1) {
                    v0 = fmaxf(v0, 0.f); v1 = fmaxf(v1, 0.f);
                    store_hl2((__nv_bfloat16*)Cout + (size_t)row * 2 * ldc, col, v0, v1);
                } else if (OUTQ == 2) {
                    if (col < 512) {
                        float s0 = v0 * ATTN_SCALE, s1 = v1 * ATTN_SCALE;
                        uint16_t h0, l0, h1, l1;
                        split_hl(s0, h0, l0); split_hl(s1, h1, l1);
                        *(uint32_t*)(qh + (size_t)row * EE + col) = pack2(h0, h1);
                        *(uint32_t*)(ql + (size_t)row * EE + col) = pack2(l0, l1);
                    } else if (col < 1024) {
                        int cc = col - 512;
                        uint16_t h0, l0, h1, l1;
                        split_hl(v0, h0, l0); split_hl(v1, h1, l1);
                        *(uint32_t*)(kh + (size_t)row * EE + cc) = pack2(h0, h1);
                        *(uint32_t*)(kl + (size_t)row * EE + cc) = pack2(l0, l1);
                    } else {
                        *(float2*)(vf + (size_t)row * EE + col - 1024) = make_float2(v0, v1);
                    }
                } else {
                    *(float2*)((float*)Cout + (size_t)row * ldc + col) = make_float2(v0, v1);
                }
            }
        }
}

// ---------------- HMMA flash attention (unchanged core; HL output) ----------------
#define ATTN_SMEM2 (98304 + 512)
__global__ __launch_bounds__(256) void attn_hmma(
    const __nv_bfloat16* __restrict__ Qh, const __nv_bfloat16* __restrict__ Ql,
    const __nv_bfloat16* __restrict__ Kh, const __nv_bfloat16* __restrict__ Kl,
    const __nv_bfloat16* __restrict__ VhT, const __nv_bfloat16* __restrict__ VlT,
    const int* __restrict__ mask, __nv_bfloat16* __restrict__ ATTHL)
{
    extern __shared__ char smem[];
    const uint32_t sb = smem_u32(smem);
    int* Ms = (int*)(smem + 98304);
    const int tid = threadIdx.x, lane = tid & 31, wid = tid >> 5;
    const int bh = blockIdx.y, b = bh >> 3, h = bh & 7;
    const int qrow0 = blockIdx.x * 128;
    const int wr = wid * 16;

    {
        const char* qhp = (const char*)(Qh + (size_t)(b * SS + qrow0) * EE + h * DH);
        const char* qlp = (const char*)(Ql + (size_t)(b * SS + qrow0) * EE + h * DH);
        #pragma unroll
        for (int i = 0; i < 4; i++) {
            int id = tid + i * 256;
            int r = id >> 3, ck = (id & 7) * 16;
            cp16(sb +         SWZ128(r * 128 + ck), qhp + (size_t)r * 1024 + ck);
            cp16(sb + 16384 + SWZ128(r * 128 + ck), qlp + (size_t)r * 1024 + ck);
        }
    }
    auto load_stage = [&](int kt) {
        uint32_t st = sb + 32768 + (kt & 1) * 32768;
        const char* khp = (const char*)(Kh + (size_t)(b * SS + kt * 64) * EE + h * DH);
        const char* klp = (const char*)(Kl + (size_t)(b * SS + kt * 64) * EE + h * DH);
        const char* vhp = (const char*)(VhT + (size_t)bh * DH * SS + kt * 64);
        const char* vlp = (const char*)(VlT + (size_t)bh * DH * SS + kt * 64);
        #pragma unroll
        for (int i = 0; i < 2; i++) {
            int id = tid + i * 256;
            int r = id >> 3, ck = (id & 7) * 16;
            cp16(st +         SWZ128(r * 128 + ck), khp + (size_t)r * 1024 + ck);
            cp16(st + 8192  + SWZ128(r * 128 + ck), klp + (size_t)r * 1024 + ck);
            cp16(st + 16384 + SWZ128(r * 128 + ck), vhp + (size_t)r * (SS * 2) + ck);
            cp16(st + 24576 + SWZ128(r * 128 + ck), vlp + (size_t)r * (SS * 2) + ck);
        }
        if (tid < 64) Ms[(kt & 1) * 64 + tid] = mask[b * SS + kt * 64 + tid];
    };

    float m_i[2] = {-INFINITY, -INFINITY}, l_i[2] = {0.f, 0.f};
    float o_acc[8][4];
    #pragma unroll
    for (int nt = 0; nt < 8; nt++)
        #pragma unroll
        for (int c = 0; c < 4; c++) o_acc[nt][c] = 0.f;

    load_stage(0); CP_COMMIT();
    const int NT = SS / 64;
    for (int kt = 0; kt < NT; kt++) {
        if (kt + 1 < NT) {
            load_stage(kt + 1); CP_COMMIT();
            asm volatile("cp.async.wait_group 1;" ::: "memory");
        } else {
            asm volatile("cp.async.wait_group 0;" ::: "memory");
        }
        __syncthreads();
        const uint32_t st = sb + 32768 + (kt & 1) * 32768;
        const uint32_t sKh = st, sKl = st + 8192, sVh = st + 16384, sVl = st + 24576;

        float s_acc[8][4];
        #pragma unroll
        for (int nt = 0; nt < 8; nt++)
            #pragma unroll
            for (int c = 0; c < 4; c++) s_acc[nt][c] = 0.f;

        #pragma unroll
        for (int kc = 0; kc < 4; kc++) {
            int bc = kc * 32;
            uint32_t qhf[4], qlf[4];
            {
                int row = wr + ((lane >> 3) & 1) * 8 + (lane & 7);
                int col = bc + (lane >> 4) * 16;
                ldsm4(qhf, sb +         SWZ128(row * 128 + col));
                ldsm4(qlf, sb + 16384 + SWZ128(row * 128 + col));
            }
            #pragma unroll
            for (int ng = 0; ng < 4; ng++) {
                uint32_t khf[4], klf[4];
                int row = ng * 16 + ((lane >> 4) & 1) * 8 + (lane & 7);
                int col = bc + ((lane >> 3) & 1) * 16;
                ldsm4(khf, sKh + SWZ128(row * 128 + col));
                ldsm4(klf, sKl + SWZ128(row * 128 + col));
                #pragma unroll
                for (int t2 = 0; t2 < 2; t2++) {
                    int nt = ng * 2 + t2;
                    mma_bf16(s_acc[nt], qhf, &khf[t2 * 2]);
                    mma_bf16(s_acc[nt], qhf, &klf[t2 * 2]);
                    mma_bf16(s_acc[nt], qlf, &khf[t2 * 2]);
                }
            }
        }

        const int t4 = (lane & 3) * 2;
        const int msb = (kt & 1) * 64;
        #pragma unroll
        for (int nt = 0; nt < 8; nt++) {
            if (Ms[msb + nt * 8 + t4] == 0)     { s_acc[nt][0] = -1e20f; s_acc[nt][2] = -1e20f; }
            if (Ms[msb + nt * 8 + t4 + 1] == 0) { s_acc[nt][1] = -1e20f; s_acc[nt][3] = -1e20f; }
        }

        #pragma unroll
        for (int r = 0; r < 2; r++) {
            float mx = -INFINITY;
            #pragma unroll
            for (int nt = 0; nt < 8; nt++)
                mx = fmaxf(mx, fmaxf(s_acc[nt][r * 2], s_acc[nt][r * 2 + 1]));
            mx = fmaxf(mx, __shfl_xor_sync(0xffffffffu, mx, 1));
            mx = fmaxf(mx, __shfl_xor_sync(0xffffffffu, mx, 2));
            float mnew = fmaxf(m_i[r], mx);
            float corr = __expf(m_i[r] - mnew);
            float rs = 0.f;
            #pragma unroll
            for (int nt = 0; nt < 8; nt++) {
                float p0 = __expf(s_acc[nt][r * 2] - mnew);
                float p1 = __expf(s_acc[nt][r * 2 + 1] - mnew);
                s_acc[nt][r * 2] = p0; s_acc[nt][r * 2 + 1] = p1;
                rs += p0 + p1;
            }
            rs += __shfl_xor_sync(0xffffffffu, rs, 1);
            rs += __shfl_xor_sync(0xffffffffu, rs, 2);
            l_i[r] = l_i[r] * corr + rs;
            m_i[r] = mnew;
            #pragma unroll
            for (int nt = 0; nt < 8; nt++) {
                o_acc[nt][r * 2] *= corr; o_acc[nt][r * 2 + 1] *= corr;
            }
        }

        #pragma unroll
        for (int kc = 0; kc < 4; kc++) {
            uint32_t ph[4], pl[4];
            {
                uint16_t h0, l0, h1, l1;
                split_hl(s_acc[2 * kc][0], h0, l0); split_hl(s_acc[2 * kc][1], h1, l1);
                ph[0] = pack2(h0, h1); pl[0] = pack2(l0, l1);
                split_hl(s_acc[2 * kc][2], h0, l0); split_hl(s_acc[2 * kc][3], h1, l1);
                ph[1] = pack2(h0, h1); pl[1] = pack2(l0, l1);
                split_hl(s_acc[2 * kc + 1][0], h0, l0); split_hl(s_acc[2 * kc + 1][1], h1, l1);
                ph[2] = pack2(h0, h1); pl[2] = pack2(l0, l1);
                split_hl(s_acc[2 * kc + 1][2], h0, l0); split_hl(s_acc[2 * kc + 1][3], h1, l1);
                ph[3] = pack2(h0, h1); pl[3] = pack2(l0, l1);
            }
            #pragma unroll
            for (int ng = 0; ng < 4; ng++) {
                uint32_t vhf[4], vlf[4];
                int row = ng * 16 + ((lane >> 4) & 1) * 8 + (lane & 7);
                int col = kc * 32 + ((lane >> 3) & 1) * 16;
                ldsm4(vhf, sVh + SWZ128(row * 128 + col));
                ldsm4(vlf, sVl + SWZ128(row * 128 + col));
                #pragma unroll
                for (int t2 = 0; t2 < 2; t2++) {
                    int nt = ng * 2 + t2;
                    mma_bf16(o_acc[nt], ph, &vhf[t2 * 2]);
                    mma_bf16(o_acc[nt], ph, &vlf[t2 * 2]);
                    mma_bf16(o_acc[nt], pl, &vhf[t2 * 2]);
                }
            }
        }
        __syncthreads();
    }

    // epilogue: write HL
    const int g = lane >> 2;
    #pragma unroll
    for (int r = 0; r < 2; r++) {
        float inv = 1.f / l_i[r];
        int row = qrow0 + wr + g + r * 8;
        __nv_bfloat16* rp = ATTHL + (size_t)(b * SS + row) * 2 * EE;
        #pragma unroll
        for (int nt = 0; nt < 8; nt++) {
            int col = h * DH + nt * 8 + (lane & 3) * 2;
            store_hl2(rp, col, o_acc[nt][r * 2] * inv, o_acc[nt][r * 2 + 1] * inv);
        }
    }
}

// ---------------- embedding (writes X + XHL) ----------------
__global__ __launch_bounds__(128) void embed_kernel(
    const float* __restrict__ seq, const float* __restrict__ W,
    const float* __restrict__ bias, const float* __restrict__ pos,
    float* __restrict__ X, __nv_bfloat16* __restrict__ XHL)
{
    int m = blockIdx.x, s = m & (SS - 1), tid = threadIdx.x;
    __shared__ float srow[FF_IN];
    if (tid < FF_IN) srow[tid] = seq[(size_t)m * FF_IN + tid];
    __syncthreads();
    int n = tid * 4;
    float4 acc = *(const float4*)(bias + n);
    float4 pv  = *(const float4*)(pos + (size_t)s * EE + n);
    acc.x += pv.x; acc.y += pv.y; acc.z += pv.z; acc.w += pv.w;
    #pragma unroll 8
    for (int f = 0; f < FF_IN; f++) {
        float sv = srow[f];
        float4 w = *(const float4*)(W + (size_t)f * EE + n);
        acc.x += sv * w.x; acc.y += sv * w.y; acc.z += sv * w.z; acc.w += sv * w.w;
    }
    *(float4*)(X + (size_t)m * EE + n) = acc;
    store_hl4(XHL + (size_t)m * 2 * EE, n, acc.x, acc.y, acc.z, acc.w);
}

// ---------------- residual + LN (optional HL out) ----------------
__global__ __launch_bounds__(128) void ln_kernel(
    const float* __restrict__ a, const float* __restrict__ br,
    const float* __restrict__ g, const float* __restrict__ be,
    float* __restrict__ out, __nv_bfloat16* __restrict__ xhl)
{
    int m = blockIdx.x, tid = threadIdx.x;
    size_t base = (size_t)m * EE + tid * 4;
    float4 va = *(const float4*)(a + base);
    float4 vb = *(const float4*)(br + base);
    float x0 = va.x + vb.x, x1 = va.y + vb.y, x2 = va.z + vb.z, x3 = va.w + vb.w;
    float s = x0 + x1 + x2 + x3;
    float ss = x0 * x0 + x1 * x1 + x2 * x2 + x3 * x3;
    #pragma unroll
    for (int off = 16; off; off >>= 1) {
        s  += __shfl_xor_sync(0xffffffffu, s, off);
        ss += __shfl_xor_sync(0xffffffffu, ss, off);
    }
    __shared__ float red[8];
    int w = tid >> 5;
    if ((tid & 31) == 0) { red[w] = s; red[4 + w] = ss; }
    __syncthreads();
    s  = red[0] + red[1] + red[2] + red[3];
    ss = red[4] + red[5] + red[6] + red[7];
    float mean = s * (1.f / EE);
    float var  = ss * (1.f / EE) - mean * mean;
    float r = rsqrtf(var + 1e-5f);
    float4 gg = *(const float4*)(g + tid * 4);
    float4 bb = *(const float4*)(be + tid * 4);
    float4 o;
    o.x = (x0 - mean) * r * gg.x + bb.x;
    o.y = (x1 - mean) * r * gg.y + bb.y;
    o.z = (x2 - mean) * r * gg.z + bb.z;
    o.w = (x3 - mean) * r * gg.w + bb.w;
    *(float4*)(out + base) = o;
    if (xhl) store_hl4(xhl + (size_t)m * 2 * EE, tid * 4, o.x, o.y, o.z, o.w);
}

// ---------------- launch ----------------
extern "C" void kernel_launch(void* const* d_in, const int* in_sizes, int n_in,
                              void* d_out, int out_size)
{
    const float* seq   = (const float*)d_in[0];
    const int*   mask  = (const int*)  d_in[1];
    const float* W_emb = (const float*)d_in[2];
    const float* b_emb = (const float*)d_in[3];
    const float* pos   = (const float*)d_in[4];
    const float* Wq    = (const float*)d_in[5];
    const float* bq    = (const float*)d_in[6];
    const float* Wk    = (const float*)d_in[7];
    const float* bk    = (const float*)d_in[8];
    const float* Wv    = (const float*)d_in[9];
    const float* bv    = (const float*)d_in[10];
    const float* Wo    = (const float*)d_in[11];
    const float* bo    = (const float*)d_in[12];
    const float* ln1g  = (const float*)d_in[13];
    const float* ln1b  = (const float*)d_in[14];
    const float* ln2g  = (const float*)d_in[15];
    const float* ln2b  = (const float*)d_in[16];
    const float* W1    = (const float*)d_in[17];
    const float* b1    = (const float*)d_in[18];
    const float* W2    = (const float*)d_in[19];
    const float* b2    = (const float*)d_in[20];
    float* out = (float*)d_out;

    float *X, *P, *Vf, *bqkv;
    __nv_bfloat16 *XHL, *ATTHL, *H1HL, *QKVWHL, *WOHL, *W1HL, *W2HL;
    __nv_bfloat16 *Qh, *Ql, *Kh, *Kl, *VhT, *VlT;
    cudaGetSymbolAddress((void**)&X,     g_X);
    cudaGetSymbolAddress((void**)&P,     g_P);
    cudaGetSymbolAddress((void**)&Vf,    g_Vf);
    cudaGetSymbolAddress((void**)&bqkv,  g_bqkv);
    cudaGetSymbolAddress((void**)&XHL,   g_XHL);
    cudaGetSymbolAddress((void**)&ATTHL, g_ATTHL);
    cudaGetSymbolAddress((void**)&H1HL,  g_H1HL);
    cudaGetSymbolAddress((void**)&QKVWHL,g_QKVWHL);
    cudaGetSymbolAddress((void**)&WOHL,  g_WOHL);
    cudaGetSymbolAddress((void**)&W1HL,  g_W1HL);
    cudaGetSymbolAddress((void**)&W2HL,  g_W2HL);
    cudaGetSymbolAddress((void**)&Qh,    g_Qh);
    cudaGetSymbolAddress((void**)&Ql,    g_Ql);
    cudaGetSymbolAddress((void**)&Kh,    g_Kh);
    cudaGetSymbolAddress((void**)&Kl,    g_Kl);
    cudaGetSymbolAddress((void**)&VhT,   g_VhT);
    cudaGetSymbolAddress((void**)&VlT,   g_VlT);

    cudaFuncSetAttribute(hl_gemm<0>, cudaFuncAttributeMaxDynamicSharedMemorySize, GSMEM);
    cudaFuncSetAttribute(hl_gemm<1>, cudaFuncAttributeMaxDynamicSharedMemorySize, GSMEM);
    cudaFuncSetAttribute(hl_gemm<2>, cudaFuncAttributeMaxDynamicSharedMemorySize, GSMEM);
    cudaFuncSetAttribute(attn_hmma, cudaFuncAttributeMaxDynamicSharedMemorySize, ATTN_SMEM2);

    biascat_kernel<<<24, 256>>>(bq, bk, bv, bqkv);
    dim3 tb(32, 8);
    // 6 prep launches, z = layer
    prepW_kernel<<<dim3(16, 16, LL), tb>>>(Wq, QKVWHL,             EE, EE, (size_t)EE * EE, (size_t)1536 * 2 * EE);
    prepW_kernel<<<dim3(16, 16, LL), tb>>>(Wk, QKVWHL + (size_t) 512 * 2 * EE, EE, EE, (size_t)EE * EE, (size_t)1536 * 2 * EE);
    prepW_kernel<<<dim3(16, 16, LL), tb>>>(Wv, QKVWHL + (size_t)1024 * 2 * EE, EE, EE, (size_t)EE * EE, (size_t)1536 * 2 * EE);
    prepW_kernel<<<dim3(16, 16, LL), tb>>>(Wo, WOHL, EE, EE, (size_t)EE * EE, (size_t)EE * 2 * EE);
    prepW_kernel<<<dim3(64, 16, LL), tb>>>(W1, W1HL, EE, FFN, (size_t)EE * FFN, (size_t)FFN * 2 * EE);
    prepW_kernel<<<dim3(16, 64, LL), tb>>>(W2, W2HL, FFN, EE, (size_t)FFN * EE, (size_t)EE * 2 * FFN);

    embed_kernel<<<MM, 128>>>(seq, W_emb, b_emb, pos, X, XHL);

    dim3 gQKV(1536 / 128, MM / 128);
    dim3 gE(EE / 128, MM / 128);
    dim3 gF(FFN / 128, MM / 128);
    dim3 attnG(SS / 128, BB * HH);

    for (int l = 0; l < LL; l++) {
        size_t oB = (size_t)l * EE, oB1 = (size_t)l * FFN;

        hl_gemm<2><<<gQKV, 256, GSMEM>>>(XHL, QKVWHL + (size_t)l * 1536 * 2 * EE,
                                         bqkv + (size_t)l * 1536, nullptr, 0, EE,
                                         Qh, Ql, Kh, Kl, Vf);
        vprep_kernel<<<dim3(MM / 64, HH), 256>>>(Vf, VhT, VlT);
        attn_hmma<<<attnG, 256, ATTN_SMEM2>>>(Qh, Ql, Kh, Kl, VhT, VlT, mask, ATTHL);

        hl_gemm<0><<<gE, 256, GSMEM>>>(ATTHL, WOHL + (size_t)l * EE * 2 * EE, bo + oB, P, EE, EE,
                                       nullptr, nullptr, nullptr, nullptr, nullptr);
        ln_kernel<<<MM, 128>>>(X, P, ln1g + oB, ln1b + oB, X, XHL);

        hl_gemm<1><<<gF, 256, GSMEM>>>(XHL, W1HL + (size_t)l * FFN * 2 * EE, b1 + oB1, H1HL, FFN, EE,
                                       nullptr, nullptr, nullptr, nullptr, nullptr);
        hl_gemm<0><<<gE, 256, GSMEM>>>(H1HL, W2HL + (size_t)l * EE * 2 * FFN, b2 + oB, P, EE, FFN,
                                       nullptr, nullptr, nullptr, nullptr, nullptr);

        float* dst = (l == LL - 1) ? out : X;
        ln_kernel<<<MM, 128>>>(X, P, ln2g + oB, ln2b + oB, dst, (l == LL - 1) ? nullptr : XHL);
    }
}